// round 13
// baseline (speedup 1.0000x reference)
#include <cuda_runtime.h>
#include <cuda_bf16.h>
#include <math.h>
#include <stdint.h>

// Problem constants
constexpr int BATCH = 8192;
constexpr int DIM   = 512;
constexpr int K8    = 8;
constexpr int NCH   = 16;
constexpr float INV_TAU = 5.0f;
constexpr float ALPHA   = 0.3f;
constexpr float LN_EPS  = 1e-5f;

// GEMM tiling (R8 proven): CTA 128x256, BK=64, double-buffered bulk-copy pipeline
constexpr int BM = 128, BN = 256, BK = 64;
constexpr int KCH = DIM / BK;
constexpr int BLKE = 128 * 64;
constexpr int BLKB = 16384;
constexpr int STAGE = 6 * BLKB;
constexpr int SMEM_DYN = 1024 + 2 * STAGE;

// ---------------- scratch ----------------
__device__ __nv_bfloat16 g_gi_h[BATCH * DIM], g_gi_l[BATCH * DIM];
__device__ __nv_bfloat16 g_gt_h[BATCH * DIM], g_gt_l[BATCH * DIM];
__device__ __nv_bfloat16 g_gIr_h[BATCH * DIM], g_gIr_l[BATCH * DIM];
__device__ __nv_bfloat16 g_gTr_h[BATCH * DIM], g_gTr_l[BATCH * DIM];
__device__ __nv_bfloat16 g_Wi_h[DIM * DIM], g_Wi_l[DIM * DIM];
__device__ __nv_bfloat16 g_Wt_h[DIM * DIM], g_Wt_l[DIM * DIM];
__device__ float g_PT[BATCH * DIM];
__device__ float g_PI[BATCH * DIM];
__device__ float g_rowW[BATCH * K8];
__device__ int   g_rowI[BATCH * K8];
__device__ float g_colW[BATCH * K8];
__device__ int   g_colI[BATCH * K8];
__device__ float g_cpV[NCH * BATCH * K8];
__device__ int   g_cpI[NCH * BATCH * K8];

// ---------------- PTX helpers ----------------
__device__ __forceinline__ uint32_t smem_u32(const void* p) {
    return (uint32_t)__cvta_generic_to_shared(p);
}
__device__ __forceinline__ void ldsm4(uint32_t* r, uint32_t a) {
    asm volatile("ldmatrix.sync.aligned.m8n8.x4.shared.b16 {%0,%1,%2,%3}, [%4];"
                 : "=r"(r[0]), "=r"(r[1]), "=r"(r[2]), "=r"(r[3]) : "r"(a));
}
__device__ __forceinline__ void mma_bf16(float* c, const uint32_t* a,
                                         uint32_t b0, uint32_t b1) {
    asm volatile("mma.sync.aligned.m16n8k16.row.col.f32.bf16.bf16.f32 "
                 "{%0,%1,%2,%3}, {%4,%5,%6,%7}, {%8,%9}, {%0,%1,%2,%3};"
                 : "+f"(c[0]), "+f"(c[1]), "+f"(c[2]), "+f"(c[3])
                 : "r"(a[0]), "r"(a[1]), "r"(a[2]), "r"(a[3]), "r"(b0), "r"(b1));
}
__device__ __forceinline__ void mbar_init(uint32_t a, uint32_t cnt) {
    asm volatile("mbarrier.init.shared.b64 [%0], %1;" :: "r"(a), "r"(cnt) : "memory");
}
__device__ __forceinline__ void mbar_expect(uint32_t a, uint32_t bytes) {
    asm volatile("mbarrier.arrive.expect_tx.shared.b64 _, [%0], %1;"
                 :: "r"(a), "r"(bytes) : "memory");
}
__device__ __forceinline__ void mbar_wait(uint32_t a, uint32_t parity) {
    uint32_t done;
    asm volatile("{\n\t.reg .pred p;\n\t"
                 "mbarrier.try_wait.parity.acquire.cta.shared::cta.b64 p, [%1], %2;\n\t"
                 "selp.b32 %0, 1, 0, p;\n\t}" : "=r"(done) : "r"(a), "r"(parity) : "memory");
    if (!done) {
        asm volatile("{\n\t.reg .pred P1;\n\t"
                     "W_%=:\n\t"
                     "mbarrier.try_wait.parity.acquire.cta.shared::cta.b64 P1, [%0], %1, 0x989680;\n\t"
                     "@P1 bra.uni D_%=;\n\t"
                     "bra.uni W_%=;\n\t"
                     "D_%=:\n\t}" :: "r"(a), "r"(parity) : "memory");
    }
}
__device__ __forceinline__ void bulk_cp(uint32_t dst, const void* src, uint32_t bytes,
                                        uint32_t mbar) {
    asm volatile("cp.async.bulk.shared::cta.global.mbarrier::complete_tx::bytes "
                 "[%0], [%1], %2, [%3];"
                 :: "r"(dst), "l"(__cvta_generic_to_global(src)), "r"(bytes), "r"(mbar)
                 : "memory");
}

// ---------------- split-bf16 GEMM on mma.sync (R8 proven, unchanged) ----------------
__global__ void __launch_bounds__(256, 1)
gemm_mma(const __nv_bfloat16* __restrict__ Ah, const __nv_bfloat16* __restrict__ Al,
         const __nv_bfloat16* __restrict__ Bh, const __nv_bfloat16* __restrict__ Bl,
         float* __restrict__ C, int ldc, float alpha)
{
    extern __shared__ char smem[];
    const uint32_t sb = smem_u32(smem);
    const uint32_t mb = sb;
    const uint32_t bufb = (sb + 1024u) & ~1023u;
    const int tid = threadIdx.x, wid = tid >> 5, lane = tid & 31;
    const int wm = wid >> 2, wn = wid & 3;
    const int bm = blockIdx.y * BM, bn = blockIdx.x * BN;
    const int g = lane >> 3, r8 = lane & 7;

    uint32_t abase[4], bbase[4];
#pragma unroll
    for (int i = 0; i < 4; i++) {
        int row = wm * 64 + i * 16 + r8 + (g & 1) * 8;
        abase[i] = (uint32_t)(row * 128);
    }
#pragma unroll
    for (int j = 0; j < 4; j++) {
        int row = wn * 64 + j * 16 + r8 + (g >> 1) * 8;
        bbase[j] = (uint32_t)((row & 127) * 128 + (row >> 7) * BLKB);
    }
    const uint32_t acsel = (uint32_t)((g >> 1) * 16);
    const uint32_t bcsel = (uint32_t)((g & 1) * 16);

    float acc[4][8][4];
#pragma unroll
    for (int i = 0; i < 4; i++)
#pragma unroll
        for (int j = 0; j < 8; j++)
#pragma unroll
            for (int q = 0; q < 4; q++) acc[i][j][q] = 0.0f;

    auto arm_load = [&](int s, int kc) {
        uint32_t mbar = mb + (uint32_t)s * 8;
        mbar_expect(mbar, STAGE);
        uint32_t st = bufb + (uint32_t)s * STAGE;
        size_t a  = ((size_t)((bm >> 7) * KCH + kc)) * BLKE;
        size_t b0 = ((size_t)((bn >> 7) * KCH + kc)) * BLKE;
        size_t b1 = ((size_t)(((bn >> 7) + 1) * KCH + kc)) * BLKE;
        bulk_cp(st,             Ah + a,  BLKB, mbar);
        bulk_cp(st + BLKB,      Al + a,  BLKB, mbar);
        bulk_cp(st + 2 * BLKB,  Bh + b0, BLKB, mbar);
        bulk_cp(st + 3 * BLKB,  Bh + b1, BLKB, mbar);
        bulk_cp(st + 4 * BLKB,  Bl + b0, BLKB, mbar);
        bulk_cp(st + 5 * BLKB,  Bl + b1, BLKB, mbar);
    };

    if (tid == 0) { mbar_init(mb, 1); mbar_init(mb + 8, 1); }
    __syncthreads();
    if (tid == 0) { arm_load(0, 0); arm_load(1, 1); }

    for (int t = 0; t < KCH; t++) {
        mbar_wait(mb + (uint32_t)(t & 1) * 8, (t >> 1) & 1);
        const uint32_t st = bufb + (uint32_t)(t & 1) * STAGE;

#pragma unroll
        for (int ks = 0; ks < 4; ks++) {
            const uint32_t ac = acsel + ks * 32;
            const uint32_t bc = bcsel + ks * 32;
            uint32_t Afr[4][4], Alf[4][4], Bhf[4][4], Blf[4][4];
#pragma unroll
            for (int i = 0; i < 4; i++) {
                uint32_t o = abase[i] + ac; o ^= (o >> 3) & 0x70;
                ldsm4(Afr[i], st + o);
            }
#pragma unroll
            for (int j = 0; j < 4; j++) {
                uint32_t o = bbase[j] + bc; o ^= (o >> 3) & 0x70;
                ldsm4(Bhf[j], st + 2 * BLKB + o);
            }
#pragma unroll
            for (int i = 0; i < 4; i++) {
                uint32_t o = abase[i] + ac; o ^= (o >> 3) & 0x70;
                ldsm4(Alf[i], st + BLKB + o);
            }
#pragma unroll
            for (int j = 0; j < 4; j++) {
                uint32_t o = bbase[j] + bc; o ^= (o >> 3) & 0x70;
                ldsm4(Blf[j], st + 4 * BLKB + o);
            }
#pragma unroll
            for (int i = 0; i < 4; i++)
#pragma unroll
                for (int j = 0; j < 4; j++) {
                    mma_bf16(acc[i][2 * j],     Afr[i], Bhf[j][0], Bhf[j][1]);
                    mma_bf16(acc[i][2 * j + 1], Afr[i], Bhf[j][2], Bhf[j][3]);
                }
#pragma unroll
            for (int i = 0; i < 4; i++)
#pragma unroll
                for (int j = 0; j < 4; j++) {
                    mma_bf16(acc[i][2 * j],     Alf[i], Bhf[j][0], Bhf[j][1]);
                    mma_bf16(acc[i][2 * j + 1], Alf[i], Bhf[j][2], Bhf[j][3]);
                }
#pragma unroll
            for (int i = 0; i < 4; i++)
#pragma unroll
                for (int j = 0; j < 4; j++) {
                    mma_bf16(acc[i][2 * j],     Afr[i], Blf[j][0], Blf[j][1]);
                    mma_bf16(acc[i][2 * j + 1], Afr[i], Blf[j][2], Blf[j][3]);
                }
        }

        __syncthreads();
        if (t + 2 < KCH && tid == 0) arm_load(t & 1, t + 2);
    }

    const int row0 = bm + wm * 64 + (lane >> 2);
    const int col0 = bn + wn * 64 + (lane & 3) * 2;
#pragma unroll
    for (int i = 0; i < 4; i++) {
#pragma unroll
        for (int j = 0; j < 8; j++) {
            int r = row0 + i * 16, cc = col0 + j * 8;
            float2 v0 = make_float2(acc[i][j][0] * alpha, acc[i][j][1] * alpha);
            float2 v1 = make_float2(acc[i][j][2] * alpha, acc[i][j][3] * alpha);
            *(float2*)&C[(size_t)r * ldc + cc]       = v0;
            *(float2*)&C[(size_t)(r + 8) * ldc + cc] = v1;
        }
    }
}

// ---------------- conversions ----------------
__device__ __forceinline__ void split_bf16(float x, __nv_bfloat16& h, __nv_bfloat16& l) {
    h = __float2bfloat16_rn(x);
    l = __float2bfloat16_rn(x - __bfloat162float(h));
}

__device__ __forceinline__ size_t blk_idx(int row, int u) {
    int rb = row >> 7, kc = u >> 3;
    uint32_t off = (uint32_t)((row & 127) * 128 + (u & 7) * 16);
    off ^= (off >> 3) & 0x70;
    return ((size_t)(rb * KCH + kc)) * BLKE + (off >> 1);
}

__global__ void rownorm_split_kernel(const float* __restrict__ X,
                                     __nv_bfloat16* __restrict__ Yh,
                                     __nv_bfloat16* __restrict__ Yl) {
    __shared__ float sbuf[256];
    __shared__ float rowv[512];
    int row = blockIdx.x, tid = threadIdx.x;
    const float* x = X + (size_t)row * DIM;
    float v0 = x[tid], v1 = x[tid + 256];
    rowv[tid] = v0; rowv[tid + 256] = v1;
    sbuf[tid] = v0 * v0 + v1 * v1;
    __syncthreads();
    for (int s = 128; s > 0; s >>= 1) {
        if (tid < s) sbuf[tid] += sbuf[tid + s];
        __syncthreads();
    }
    float inv = 1.0f / fmaxf(sqrtf(sbuf[0]), 1e-12f);
    if (tid < 128) {
        int u = tid & 63;
        bool hi = tid < 64;
        __nv_bfloat16 out[8];
#pragma unroll
        for (int e = 0; e < 8; e++) {
            float v = rowv[u * 8 + e] * inv;
            __nv_bfloat16 h, l;
            split_bf16(v, h, l);
            out[e] = hi ? h : l;
        }
        size_t idx = blk_idx(row, u);
        *(uint4*)((hi ? Yh : Yl) + idx) = *(uint4*)out;
    }
}

constexpr int NBIG = BATCH * DIM;
constexpr int NW   = DIM * DIM;
constexpr int U_BIG = NBIG / 8;
constexpr int U_W   = NW / 8;
__global__ void split_all_kernel(const float* __restrict__ gI, const float* __restrict__ gT,
                                 const float* __restrict__ Wi, const float* __restrict__ Wt) {
    int gidx = blockIdx.x * blockDim.x + threadIdx.x;
    const float* src; __nv_bfloat16 *H, *L; int unit;
    if (gidx < U_BIG)                { src = gI; H = g_gIr_h; L = g_gIr_l; unit = gidx; }
    else if (gidx < 2 * U_BIG)       { src = gT; H = g_gTr_h; L = g_gTr_l; unit = gidx - U_BIG; }
    else if (gidx < 2 * U_BIG + U_W) { src = Wi; H = g_Wi_h;  L = g_Wi_l;  unit = gidx - 2 * U_BIG; }
    else                             { src = Wt; H = g_Wt_h;  L = g_Wt_l;  unit = gidx - 2 * U_BIG - U_W; }
    int row = unit >> 6, u = unit & 63;
    const float4* s4 = (const float4*)(src + (size_t)row * DIM + u * 8);
    float4 a = s4[0], b = s4[1];
    float vals[8] = {a.x, a.y, a.z, a.w, b.x, b.y, b.z, b.w};
    __nv_bfloat16 h[8], l[8];
#pragma unroll
    for (int e = 0; e < 8; e++) split_bf16(vals[e], h[e], l[e]);
    size_t idx = blk_idx(row, u);
    *(uint4*)(H + idx) = *(uint4*)h;
    *(uint4*)(L + idx) = *(uint4*)l;
}

// ---------------- top-8 merge network helpers ----------------
__device__ __forceinline__ void ce_desc(float* d, int* di, int i, int j) {
    if (d[j] > d[i]) {
        float tv = d[i]; d[i] = d[j]; d[j] = tv;
        int tb = di[i]; di[i] = di[j]; di[j] = tb;
    }
}
__device__ __forceinline__ void bitonic_resort8(float* d, int* di) {
    ce_desc(d, di, 0, 4); ce_desc(d, di, 1, 5); ce_desc(d, di, 2, 6); ce_desc(d, di, 3, 7);
    ce_desc(d, di, 0, 2); ce_desc(d, di, 1, 3); ce_desc(d, di, 4, 6); ce_desc(d, di, 5, 7);
    ce_desc(d, di, 0, 1); ce_desc(d, di, 2, 3); ce_desc(d, di, 4, 5); ce_desc(d, di, 6, 7);
}
__device__ __forceinline__ void shfl_merge8(float* d, int* di, int off) {
    float pd[K8]; int pdi[K8];
#pragma unroll
    for (int i = 0; i < K8; i++) {
        pd[i]  = __shfl_xor_sync(0xffffffffu, d[i], off);
        pdi[i] = __shfl_xor_sync(0xffffffffu, di[i], off);
    }
#pragma unroll
    for (int i = 0; i < K8; i++) {
        if (pd[K8 - 1 - i] > d[i]) { d[i] = pd[K8 - 1 - i]; di[i] = pdi[K8 - 1 - i]; }
    }
    bitonic_resort8(d, di);
}

// ---------------- row top-8 + softmax ----------------
__global__ void row_topk_kernel(const float* __restrict__ S) {
    __shared__ float sv[8 * K8];
    __shared__ int   si[8 * K8];
    const int row = blockIdx.x, tid = threadIdx.x;
    const int wid = tid >> 5, lane = tid & 31;
    const float4* Sr4 = (const float4*)(S + (size_t)row * BATCH);

    float tv[K8]; int ti[K8];
#pragma unroll
    for (int t = 0; t < K8; t++) { tv[t] = -1e30f; ti[t] = 0; }

#pragma unroll
    for (int it = 0; it < BATCH / 1024; it++) {
        float4 v = Sr4[it * 256 + tid];
        float m4 = fmaxf(fmaxf(v.x, v.y), fmaxf(v.z, v.w));
        if (m4 > tv[0]) {
            int base = (it * 256 + tid) * 4;
            float vals[4] = {v.x, v.y, v.z, v.w};
#pragma unroll
            for (int e = 0; e < 4; e++) {
                float x = vals[e];
                if (x > tv[0]) {
                    tv[0] = x; ti[0] = base + e;
#pragma unroll
                    for (int q = 0; q < K8 - 1; q++) {
                        if (tv[q] > tv[q + 1]) {
                            float a = tv[q]; tv[q] = tv[q + 1]; tv[q + 1] = a;
                            int b = ti[q]; ti[q] = ti[q + 1]; ti[q + 1] = b;
                        }
                    }
                }
            }
        }
    }

    float d[K8]; int di[K8];
#pragma unroll
    for (int i = 0; i < K8; i++) { d[i] = tv[K8 - 1 - i]; di[i] = ti[K8 - 1 - i]; }

    shfl_merge8(d, di, 16);
    shfl_merge8(d, di, 8);
    shfl_merge8(d, di, 4);
    shfl_merge8(d, di, 2);
    shfl_merge8(d, di, 1);

    if (lane == 0) {
#pragma unroll
        for (int i = 0; i < K8; i++) { sv[wid * K8 + i] = d[i]; si[wid * K8 + i] = di[i]; }
    }
    __syncthreads();

    if (wid == 0) {
        int src = lane & 7;
#pragma unroll
        for (int i = 0; i < K8; i++) { d[i] = sv[src * K8 + i]; di[i] = si[src * K8 + i]; }
        shfl_merge8(d, di, 4);
        shfl_merge8(d, di, 2);
        shfl_merge8(d, di, 1);
        if (lane == 0) {
            float w[K8]; float s = 0.0f;
#pragma unroll
            for (int j = 0; j < K8; j++) { w[j] = expf(d[j] - d[0]); s += w[j]; }
            float inv = 1.0f / s;
#pragma unroll
            for (int j = 0; j < K8; j++) {
                g_rowW[row * K8 + j] = w[j] * inv;
                g_rowI[row * K8 + j] = di[j];
            }
        }
    }
}

// ---------------- column top-8 ----------------
__global__ void col_topk_part(const float* __restrict__ S) {
    const int c  = blockIdx.x * blockDim.x + threadIdx.x;
    const int ch = blockIdx.y;
    const int rows = BATCH / NCH;
    const int r0 = ch * rows;

    float tv[K8]; int ti[K8];
#pragma unroll
    for (int t = 0; t < K8; t++) { tv[t] = -1e30f; ti[t] = 0; }

    const float* p = S + (size_t)r0 * BATCH + c;
    for (int r = 0; r < rows; r += 4) {
        float vals[4];
        vals[0] = p[(size_t)(r + 0) * BATCH];
        vals[1] = p[(size_t)(r + 1) * BATCH];
        vals[2] = p[(size_t)(r + 2) * BATCH];
        vals[3] = p[(size_t)(r + 3) * BATCH];
        float m4 = fmaxf(fmaxf(vals[0], vals[1]), fmaxf(vals[2], vals[3]));
        if (m4 > tv[0]) {
#pragma unroll
            for (int e = 0; e < 4; e++) {
                float v = vals[e];
                if (v > tv[0]) {
                    tv[0] = v; ti[0] = r0 + r + e;
#pragma unroll
                    for (int q = 0; q < K8 - 1; q++) {
                        if (tv[q] > tv[q + 1]) {
                            float a = tv[q]; tv[q] = tv[q + 1]; tv[q + 1] = a;
                            int b = ti[q]; ti[q] = ti[q + 1]; ti[q + 1] = b;
                        }
                    }
                }
            }
        }
    }
    size_t base = ((size_t)ch * BATCH + c) * K8;
#pragma unroll
    for (int t = 0; t < K8; t++) { g_cpV[base + t] = tv[t]; g_cpI[base + t] = ti[t]; }
}

__global__ void col_merge_softmax() {
    const int c = blockIdx.x * blockDim.x + threadIdx.x;
    float tv[K8]; int ti[K8];
#pragma unroll
    for (int t = 0; t < K8; t++) { tv[t] = -1e30f; ti[t] = 0; }

    for (int ch = 0; ch < NCH; ch++) {
        size_t base = ((size_t)ch * BATCH + c) * K8;
#pragma unroll
        for (int t = 0; t < K8; t++) {
            float v = g_cpV[base + t];
            if (v > tv[0]) {
                int vi = g_cpI[base + t];
                tv[0] = v; ti[0] = vi;
#pragma unroll
                for (int q = 0; q < K8 - 1; q++) {
                    if (tv[q] > tv[q + 1]) {
                        float a = tv[q]; tv[q] = tv[q + 1]; tv[q + 1] = a;
                        int b = ti[q]; ti[q] = ti[q + 1]; ti[q + 1] = b;
                    }
                }
            }
        }
    }
    float mx = tv[K8 - 1];
    float w[K8]; float s = 0.0f;
#pragma unroll
    for (int t = 0; t < K8; t++) { w[t] = expf(tv[t] - mx); s += w[t]; }
    float inv = 1.0f / s;
#pragma unroll
    for (int t = 0; t < K8; t++) {
        g_colW[c * K8 + t] = w[t] * inv;
        g_colI[c * K8 + t] = ti[t];
    }
}

// ---------------- sparse message + residual + LayerNorm ----------------
__global__ void msg_ln_kernel(const float* __restrict__ X, const float* __restrict__ P,
                              const float* __restrict__ W, const int* __restrict__ IDX,
                              const float* __restrict__ gamma, const float* __restrict__ beta,
                              float* __restrict__ out) {
    __shared__ float sbuf[256];
    __shared__ float sw[K8];
    __shared__ int   sidx[K8];
    const int row = blockIdx.x, tid = threadIdx.x;
    if (tid < K8) { sw[tid] = W[row * K8 + tid]; sidx[tid] = IDX[row * K8 + tid]; }
    __syncthreads();

    float m0 = 0.0f, m1 = 0.0f;
#pragma unroll
    for (int j = 0; j < K8; j++) {
        const float* pr = P + (size_t)sidx[j] * DIM;
        float w = sw[j];
        m0 = fmaf(w, pr[tid], m0);
        m1 = fmaf(w, pr[tid + 256], m1);
    }
    float x0 = X[(size_t)row * DIM + tid]       + ALPHA * m0;
    float x1 = X[(size_t)row * DIM + tid + 256] + ALPHA * m1;

    sbuf[tid] = x0 + x1;
    __syncthreads();
    for (int s = 128; s > 0; s >>= 1) { if (tid < s) sbuf[tid] += sbuf[tid + s]; __syncthreads(); }
    float mu = sbuf[0] * (1.0f / DIM);
    __syncthreads();

    float d0 = x0 - mu, d1 = x1 - mu;
    sbuf[tid] = d0 * d0 + d1 * d1;
    __syncthreads();
    for (int s = 128; s > 0; s >>= 1) { if (tid < s) sbuf[tid] += sbuf[tid + s]; __syncthreads(); }
    float var = sbuf[0] * (1.0f / DIM);
    float rstd = rsqrtf(var + LN_EPS);

    out[(size_t)row * DIM + tid]       = d0 * rstd * gamma[tid]       + beta[tid];
    out[(size_t)row * DIM + tid + 256] = d1 * rstd * gamma[tid + 256] + beta[tid + 256];
}

// ---------------- launch: serial critical path, projections overlapped with top-k ----------------
extern "C" void kernel_launch(void* const* d_in, const int* in_sizes, int n_in,
                              void* d_out, int out_size) {
    const float* gI      = (const float*)d_in[0];
    const float* gT      = (const float*)d_in[1];
    const float* Wi      = (const float*)d_in[2];
    const float* Wt      = (const float*)d_in[3];
    const float* gamma_i = (const float*)d_in[4];
    const float* beta_i  = (const float*)d_in[5];
    const float* gamma_t = (const float*)d_in[6];
    const float* beta_t  = (const float*)d_in[7];

    float* out = (float*)d_out;
    float* gI2 = out;
    float* gT2 = out + (size_t)BATCH * DIM;
    float* S   = out + 2 * (size_t)BATCH * DIM;

    cudaFuncSetAttribute(gemm_mma, cudaFuncAttributeMaxDynamicSharedMemorySize, SMEM_DYN);

    static cudaStream_t s1 = nullptr;
    static cudaEvent_t eS = nullptr, eProj = nullptr;
    if (s1 == nullptr) {
        cudaStreamCreateWithFlags(&s1, cudaStreamNonBlocking);
        cudaEventCreateWithFlags(&eS,    cudaEventDisableTiming);
        cudaEventCreateWithFlags(&eProj, cudaEventDisableTiming);
    }

    void *p_gi_h, *p_gi_l, *p_gt_h, *p_gt_l;
    void *p_gIr_h, *p_gIr_l, *p_gTr_h, *p_gTr_l;
    void *p_Wi_h, *p_Wi_l, *p_Wt_h, *p_Wt_l;
    void *p_PT, *p_PI, *p_rowW, *p_rowI, *p_colW, *p_colI;
    cudaGetSymbolAddress(&p_gi_h, g_gi_h);   cudaGetSymbolAddress(&p_gi_l, g_gi_l);
    cudaGetSymbolAddress(&p_gt_h, g_gt_h);   cudaGetSymbolAddress(&p_gt_l, g_gt_l);
    cudaGetSymbolAddress(&p_gIr_h, g_gIr_h); cudaGetSymbolAddress(&p_gIr_l, g_gIr_l);
    cudaGetSymbolAddress(&p_gTr_h, g_gTr_h); cudaGetSymbolAddress(&p_gTr_l, g_gTr_l);
    cudaGetSymbolAddress(&p_Wi_h, g_Wi_h);   cudaGetSymbolAddress(&p_Wi_l, g_Wi_l);
    cudaGetSymbolAddress(&p_Wt_h, g_Wt_h);   cudaGetSymbolAddress(&p_Wt_l, g_Wt_l);
    cudaGetSymbolAddress(&p_PT, g_PT);       cudaGetSymbolAddress(&p_PI, g_PI);
    cudaGetSymbolAddress(&p_rowW, g_rowW);   cudaGetSymbolAddress(&p_rowI, g_rowI);
    cudaGetSymbolAddress(&p_colW, g_colW);   cudaGetSymbolAddress(&p_colI, g_colI);

    // ---- serial critical path (main stream) ----
    rownorm_split_kernel<<<BATCH, 256>>>(gI, (__nv_bfloat16*)p_gi_h, (__nv_bfloat16*)p_gi_l);
    rownorm_split_kernel<<<BATCH, 256>>>(gT, (__nv_bfloat16*)p_gt_h, (__nv_bfloat16*)p_gt_l);
    constexpr int NTOT = 2 * U_BIG + 2 * U_W;
    split_all_kernel<<<NTOT / 256, 256>>>(gI, gT, Wi, Wt);
    gemm_mma<<<dim3(BATCH / BN, BATCH / BM), 256, SMEM_DYN>>>(
        (const __nv_bfloat16*)p_gi_h, (const __nv_bfloat16*)p_gi_l,
        (const __nv_bfloat16*)p_gt_h, (const __nv_bfloat16*)p_gt_l,
        S, BATCH, INV_TAU);
    cudaEventRecord(eS, 0);

    // ---- fork: projections on s1, overlapped with top-k on main ----
    cudaStreamWaitEvent(s1, eS, 0);
    gemm_mma<<<dim3(DIM / BN, BATCH / BM), 256, SMEM_DYN, s1>>>(
        (const __nv_bfloat16*)p_gTr_h, (const __nv_bfloat16*)p_gTr_l,
        (const __nv_bfloat16*)p_Wt_h,  (const __nv_bfloat16*)p_Wt_l,
        (float*)p_PT, DIM, 1.0f);
    gemm_mma<<<dim3(DIM / BN, BATCH / BM), 256, SMEM_DYN, s1>>>(
        (const __nv_bfloat16*)p_gIr_h, (const __nv_bfloat16*)p_gIr_l,
        (const __nv_bfloat16*)p_Wi_h,  (const __nv_bfloat16*)p_Wi_l,
        (float*)p_PI, DIM, 1.0f);
    cudaEventRecord(eProj, s1);

    // main: top-k pipeline (memory-latency-bound, no smem -> co-resides with gemms)
    row_topk_kernel<<<BATCH, 256>>>(S);
    col_topk_part<<<dim3(BATCH / 256, NCH), 256>>>(S);
    col_merge_softmax<<<BATCH / 256, 256>>>();

    // join: need PT/PI before the message+LN kernels
    cudaStreamWaitEvent(0, eProj, 0);
    msg_ln_kernel<<<BATCH, 256>>>(gI, (const float*)p_PT, (const float*)p_rowW,
                                  (const int*)p_rowI, gamma_i, beta_i, gI2);
    msg_ln_kernel<<<BATCH, 256>>>(gT, (const float*)p_PI, (const float*)p_colW,
                                  (const int*)p_colI, gamma_t, beta_t, gT2);
}

// round 14
// speedup vs baseline: 1.1278x; 1.1278x over previous
#include <cuda_runtime.h>
#include <cuda_bf16.h>
#include <math.h>
#include <stdint.h>

// Problem constants
constexpr int BATCH = 8192;
constexpr int DIM   = 512;
constexpr int K8    = 8;
constexpr int NCH   = 16;
constexpr float INV_TAU = 5.0f;
constexpr float ALPHA   = 0.3f;
constexpr float LN_EPS  = 1e-5f;

// GEMM tiling (R8 proven): CTA 128x256, BK=64, double-buffered bulk-copy pipeline
constexpr int BM = 128, BN = 256, BK = 64;
constexpr int KCH = DIM / BK;
constexpr int BLKE = 128 * 64;
constexpr int BLKB = 16384;
constexpr int STAGE = 6 * BLKB;
constexpr int SMEM_DYN = 1024 + 2 * STAGE;

// ---------------- scratch ----------------
__device__ __nv_bfloat16 g_gi_h[BATCH * DIM], g_gi_l[BATCH * DIM];
__device__ __nv_bfloat16 g_gt_h[BATCH * DIM], g_gt_l[BATCH * DIM];
__device__ __nv_bfloat16 g_gIr_h[BATCH * DIM], g_gIr_l[BATCH * DIM];
__device__ __nv_bfloat16 g_gTr_h[BATCH * DIM], g_gTr_l[BATCH * DIM];
__device__ __nv_bfloat16 g_Wi_h[DIM * DIM], g_Wi_l[DIM * DIM];
__device__ __nv_bfloat16 g_Wt_h[DIM * DIM], g_Wt_l[DIM * DIM];
__device__ float g_PT[BATCH * DIM];
__device__ float g_PI[BATCH * DIM];
__device__ float g_rowW[BATCH * K8];
__device__ int   g_rowI[BATCH * K8];
__device__ float g_colW[BATCH * K8];
__device__ int   g_colI[BATCH * K8];
__device__ float g_cpV[NCH * BATCH * K8];
__device__ int   g_cpI[NCH * BATCH * K8];

// ---------------- PTX helpers ----------------
__device__ __forceinline__ uint32_t smem_u32(const void* p) {
    return (uint32_t)__cvta_generic_to_shared(p);
}
__device__ __forceinline__ void ldsm4(uint32_t* r, uint32_t a) {
    asm volatile("ldmatrix.sync.aligned.m8n8.x4.shared.b16 {%0,%1,%2,%3}, [%4];"
                 : "=r"(r[0]), "=r"(r[1]), "=r"(r[2]), "=r"(r[3]) : "r"(a));
}
__device__ __forceinline__ void mma_bf16(float* c, const uint32_t* a,
                                         uint32_t b0, uint32_t b1) {
    asm volatile("mma.sync.aligned.m16n8k16.row.col.f32.bf16.bf16.f32 "
                 "{%0,%1,%2,%3}, {%4,%5,%6,%7}, {%8,%9}, {%0,%1,%2,%3};"
                 : "+f"(c[0]), "+f"(c[1]), "+f"(c[2]), "+f"(c[3])
                 : "r"(a[0]), "r"(a[1]), "r"(a[2]), "r"(a[3]), "r"(b0), "r"(b1));
}
__device__ __forceinline__ void mbar_init(uint32_t a, uint32_t cnt) {
    asm volatile("mbarrier.init.shared.b64 [%0], %1;" :: "r"(a), "r"(cnt) : "memory");
}
__device__ __forceinline__ void mbar_expect(uint32_t a, uint32_t bytes) {
    asm volatile("mbarrier.arrive.expect_tx.shared.b64 _, [%0], %1;"
                 :: "r"(a), "r"(bytes) : "memory");
}
__device__ __forceinline__ void mbar_wait(uint32_t a, uint32_t parity) {
    uint32_t done;
    asm volatile("{\n\t.reg .pred p;\n\t"
                 "mbarrier.try_wait.parity.acquire.cta.shared::cta.b64 p, [%1], %2;\n\t"
                 "selp.b32 %0, 1, 0, p;\n\t}" : "=r"(done) : "r"(a), "r"(parity) : "memory");
    if (!done) {
        asm volatile("{\n\t.reg .pred P1;\n\t"
                     "W_%=:\n\t"
                     "mbarrier.try_wait.parity.acquire.cta.shared::cta.b64 P1, [%0], %1, 0x989680;\n\t"
                     "@P1 bra.uni D_%=;\n\t"
                     "bra.uni W_%=;\n\t"
                     "D_%=:\n\t}" :: "r"(a), "r"(parity) : "memory");
    }
}
__device__ __forceinline__ void bulk_cp(uint32_t dst, const void* src, uint32_t bytes,
                                        uint32_t mbar) {
    asm volatile("cp.async.bulk.shared::cta.global.mbarrier::complete_tx::bytes "
                 "[%0], [%1], %2, [%3];"
                 :: "r"(dst), "l"(__cvta_generic_to_global(src)), "r"(bytes), "r"(mbar)
                 : "memory");
}

// ---------------- split-bf16 GEMM on mma.sync (R8 proven, unchanged) ----------------
__global__ void __launch_bounds__(256, 1)
gemm_mma(const __nv_bfloat16* __restrict__ Ah, const __nv_bfloat16* __restrict__ Al,
         const __nv_bfloat16* __restrict__ Bh, const __nv_bfloat16* __restrict__ Bl,
         float* __restrict__ C, int ldc, float alpha)
{
    extern __shared__ char smem[];
    const uint32_t sb = smem_u32(smem);
    const uint32_t mb = sb;
    const uint32_t bufb = (sb + 1024u) & ~1023u;
    const int tid = threadIdx.x, wid = tid >> 5, lane = tid & 31;
    const int wm = wid >> 2, wn = wid & 3;
    const int bm = blockIdx.y * BM, bn = blockIdx.x * BN;
    const int g = lane >> 3, r8 = lane & 7;

    uint32_t abase[4], bbase[4];
#pragma unroll
    for (int i = 0; i < 4; i++) {
        int row = wm * 64 + i * 16 + r8 + (g & 1) * 8;
        abase[i] = (uint32_t)(row * 128);
    }
#pragma unroll
    for (int j = 0; j < 4; j++) {
        int row = wn * 64 + j * 16 + r8 + (g >> 1) * 8;
        bbase[j] = (uint32_t)((row & 127) * 128 + (row >> 7) * BLKB);
    }
    const uint32_t acsel = (uint32_t)((g >> 1) * 16);
    const uint32_t bcsel = (uint32_t)((g & 1) * 16);

    float acc[4][8][4];
#pragma unroll
    for (int i = 0; i < 4; i++)
#pragma unroll
        for (int j = 0; j < 8; j++)
#pragma unroll
            for (int q = 0; q < 4; q++) acc[i][j][q] = 0.0f;

    auto arm_load = [&](int s, int kc) {
        uint32_t mbar = mb + (uint32_t)s * 8;
        mbar_expect(mbar, STAGE);
        uint32_t st = bufb + (uint32_t)s * STAGE;
        size_t a  = ((size_t)((bm >> 7) * KCH + kc)) * BLKE;
        size_t b0 = ((size_t)((bn >> 7) * KCH + kc)) * BLKE;
        size_t b1 = ((size_t)(((bn >> 7) + 1) * KCH + kc)) * BLKE;
        bulk_cp(st,             Ah + a,  BLKB, mbar);
        bulk_cp(st + BLKB,      Al + a,  BLKB, mbar);
        bulk_cp(st + 2 * BLKB,  Bh + b0, BLKB, mbar);
        bulk_cp(st + 3 * BLKB,  Bh + b1, BLKB, mbar);
        bulk_cp(st + 4 * BLKB,  Bl + b0, BLKB, mbar);
        bulk_cp(st + 5 * BLKB,  Bl + b1, BLKB, mbar);
    };

    if (tid == 0) { mbar_init(mb, 1); mbar_init(mb + 8, 1); }
    __syncthreads();
    if (tid == 0) { arm_load(0, 0); arm_load(1, 1); }

    for (int t = 0; t < KCH; t++) {
        mbar_wait(mb + (uint32_t)(t & 1) * 8, (t >> 1) & 1);
        const uint32_t st = bufb + (uint32_t)(t & 1) * STAGE;

#pragma unroll
        for (int ks = 0; ks < 4; ks++) {
            const uint32_t ac = acsel + ks * 32;
            const uint32_t bc = bcsel + ks * 32;
            uint32_t Afr[4][4], Alf[4][4], Bhf[4][4], Blf[4][4];
#pragma unroll
            for (int i = 0; i < 4; i++) {
                uint32_t o = abase[i] + ac; o ^= (o >> 3) & 0x70;
                ldsm4(Afr[i], st + o);
            }
#pragma unroll
            for (int j = 0; j < 4; j++) {
                uint32_t o = bbase[j] + bc; o ^= (o >> 3) & 0x70;
                ldsm4(Bhf[j], st + 2 * BLKB + o);
            }
#pragma unroll
            for (int i = 0; i < 4; i++) {
                uint32_t o = abase[i] + ac; o ^= (o >> 3) & 0x70;
                ldsm4(Alf[i], st + BLKB + o);
            }
#pragma unroll
            for (int j = 0; j < 4; j++) {
                uint32_t o = bbase[j] + bc; o ^= (o >> 3) & 0x70;
                ldsm4(Blf[j], st + 4 * BLKB + o);
            }
#pragma unroll
            for (int i = 0; i < 4; i++)
#pragma unroll
                for (int j = 0; j < 4; j++) {
                    mma_bf16(acc[i][2 * j],     Afr[i], Bhf[j][0], Bhf[j][1]);
                    mma_bf16(acc[i][2 * j + 1], Afr[i], Bhf[j][2], Bhf[j][3]);
                }
#pragma unroll
            for (int i = 0; i < 4; i++)
#pragma unroll
                for (int j = 0; j < 4; j++) {
                    mma_bf16(acc[i][2 * j],     Alf[i], Bhf[j][0], Bhf[j][1]);
                    mma_bf16(acc[i][2 * j + 1], Alf[i], Bhf[j][2], Bhf[j][3]);
                }
#pragma unroll
            for (int i = 0; i < 4; i++)
#pragma unroll
                for (int j = 0; j < 4; j++) {
                    mma_bf16(acc[i][2 * j],     Afr[i], Blf[j][0], Blf[j][1]);
                    mma_bf16(acc[i][2 * j + 1], Afr[i], Blf[j][2], Blf[j][3]);
                }
        }

        __syncthreads();
        if (t + 2 < KCH && tid == 0) arm_load(t & 1, t + 2);
    }

    const int row0 = bm + wm * 64 + (lane >> 2);
    const int col0 = bn + wn * 64 + (lane & 3) * 2;
#pragma unroll
    for (int i = 0; i < 4; i++) {
#pragma unroll
        for (int j = 0; j < 8; j++) {
            int r = row0 + i * 16, cc = col0 + j * 8;
            float2 v0 = make_float2(acc[i][j][0] * alpha, acc[i][j][1] * alpha);
            float2 v1 = make_float2(acc[i][j][2] * alpha, acc[i][j][3] * alpha);
            *(float2*)&C[(size_t)r * ldc + cc]       = v0;
            *(float2*)&C[(size_t)(r + 8) * ldc + cc] = v1;
        }
    }
}

// ---------------- conversions ----------------
__device__ __forceinline__ void split_bf16(float x, __nv_bfloat16& h, __nv_bfloat16& l) {
    h = __float2bfloat16_rn(x);
    l = __float2bfloat16_rn(x - __bfloat162float(h));
}

__device__ __forceinline__ size_t blk_idx(int row, int u) {
    int rb = row >> 7, kc = u >> 3;
    uint32_t off = (uint32_t)((row & 127) * 128 + (u & 7) * 16);
    off ^= (off >> 3) & 0x70;
    return ((size_t)(rb * KCH + kc)) * BLKE + (off >> 1);
}

__global__ void rownorm_split_kernel(const float* __restrict__ X,
                                     __nv_bfloat16* __restrict__ Yh,
                                     __nv_bfloat16* __restrict__ Yl) {
    __shared__ float sbuf[256];
    __shared__ float rowv[512];
    int row = blockIdx.x, tid = threadIdx.x;
    const float* x = X + (size_t)row * DIM;
    float v0 = x[tid], v1 = x[tid + 256];
    rowv[tid] = v0; rowv[tid + 256] = v1;
    sbuf[tid] = v0 * v0 + v1 * v1;
    __syncthreads();
    for (int s = 128; s > 0; s >>= 1) {
        if (tid < s) sbuf[tid] += sbuf[tid + s];
        __syncthreads();
    }
    float inv = 1.0f / fmaxf(sqrtf(sbuf[0]), 1e-12f);
    if (tid < 128) {
        int u = tid & 63;
        bool hi = tid < 64;
        __nv_bfloat16 out[8];
#pragma unroll
        for (int e = 0; e < 8; e++) {
            float v = rowv[u * 8 + e] * inv;
            __nv_bfloat16 h, l;
            split_bf16(v, h, l);
            out[e] = hi ? h : l;
        }
        size_t idx = blk_idx(row, u);
        *(uint4*)((hi ? Yh : Yl) + idx) = *(uint4*)out;
    }
}

constexpr int NBIG = BATCH * DIM;
constexpr int NW   = DIM * DIM;
constexpr int U_BIG = NBIG / 8;
constexpr int U_W   = NW / 8;
__global__ void split_all_kernel(const float* __restrict__ gI, const float* __restrict__ gT,
                                 const float* __restrict__ Wi, const float* __restrict__ Wt) {
    int gidx = blockIdx.x * blockDim.x + threadIdx.x;
    const float* src; __nv_bfloat16 *H, *L; int unit;
    if (gidx < U_BIG)                { src = gI; H = g_gIr_h; L = g_gIr_l; unit = gidx; }
    else if (gidx < 2 * U_BIG)       { src = gT; H = g_gTr_h; L = g_gTr_l; unit = gidx - U_BIG; }
    else if (gidx < 2 * U_BIG + U_W) { src = Wi; H = g_Wi_h;  L = g_Wi_l;  unit = gidx - 2 * U_BIG; }
    else                             { src = Wt; H = g_Wt_h;  L = g_Wt_l;  unit = gidx - 2 * U_BIG - U_W; }
    int row = unit >> 6, u = unit & 63;
    const float4* s4 = (const float4*)(src + (size_t)row * DIM + u * 8);
    float4 a = s4[0], b = s4[1];
    float vals[8] = {a.x, a.y, a.z, a.w, b.x, b.y, b.z, b.w};
    __nv_bfloat16 h[8], l[8];
#pragma unroll
    for (int e = 0; e < 8; e++) split_bf16(vals[e], h[e], l[e]);
    size_t idx = blk_idx(row, u);
    *(uint4*)(H + idx) = *(uint4*)h;
    *(uint4*)(L + idx) = *(uint4*)l;
}

// ---------------- top-8 merge network helpers ----------------
__device__ __forceinline__ void ce_desc(float* d, int* di, int i, int j) {
    if (d[j] > d[i]) {
        float tv = d[i]; d[i] = d[j]; d[j] = tv;
        int tb = di[i]; di[i] = di[j]; di[j] = tb;
    }
}
__device__ __forceinline__ void bitonic_resort8(float* d, int* di) {
    ce_desc(d, di, 0, 4); ce_desc(d, di, 1, 5); ce_desc(d, di, 2, 6); ce_desc(d, di, 3, 7);
    ce_desc(d, di, 0, 2); ce_desc(d, di, 1, 3); ce_desc(d, di, 4, 6); ce_desc(d, di, 5, 7);
    ce_desc(d, di, 0, 1); ce_desc(d, di, 2, 3); ce_desc(d, di, 4, 5); ce_desc(d, di, 6, 7);
}
__device__ __forceinline__ void shfl_merge8(float* d, int* di, int off) {
    float pd[K8]; int pdi[K8];
#pragma unroll
    for (int i = 0; i < K8; i++) {
        pd[i]  = __shfl_xor_sync(0xffffffffu, d[i], off);
        pdi[i] = __shfl_xor_sync(0xffffffffu, di[i], off);
    }
#pragma unroll
    for (int i = 0; i < K8; i++) {
        if (pd[K8 - 1 - i] > d[i]) { d[i] = pd[K8 - 1 - i]; di[i] = pdi[K8 - 1 - i]; }
    }
    bitonic_resort8(d, di);
}

// ---------------- row top-8 + softmax (all 8 loads hoisted: MLP=8) ----------------
__global__ void row_topk_kernel(const float* __restrict__ S) {
    __shared__ float sv[8 * K8];
    __shared__ int   si[8 * K8];
    const int row = blockIdx.x, tid = threadIdx.x;
    const int wid = tid >> 5, lane = tid & 31;
    const float4* Sr4 = (const float4*)(S + (size_t)row * BATCH);

    // hoist all 8 float4 loads (independent addresses -> 8 in flight)
    float4 v[8];
#pragma unroll
    for (int it = 0; it < 8; it++) v[it] = Sr4[it * 256 + tid];

    float tv[K8]; int ti[K8];
#pragma unroll
    for (int t = 0; t < K8; t++) { tv[t] = -1e30f; ti[t] = 0; }

#pragma unroll
    for (int it = 0; it < 8; it++) {
        float m4 = fmaxf(fmaxf(v[it].x, v[it].y), fmaxf(v[it].z, v[it].w));
        if (m4 > tv[0]) {
            int base = (it * 256 + tid) * 4;
            float vals[4] = {v[it].x, v[it].y, v[it].z, v[it].w};
#pragma unroll
            for (int e = 0; e < 4; e++) {
                float x = vals[e];
                if (x > tv[0]) {
                    tv[0] = x; ti[0] = base + e;
#pragma unroll
                    for (int q = 0; q < K8 - 1; q++) {
                        if (tv[q] > tv[q + 1]) {
                            float a = tv[q]; tv[q] = tv[q + 1]; tv[q + 1] = a;
                            int b = ti[q]; ti[q] = ti[q + 1]; ti[q + 1] = b;
                        }
                    }
                }
            }
        }
    }

    float d[K8]; int di[K8];
#pragma unroll
    for (int i = 0; i < K8; i++) { d[i] = tv[K8 - 1 - i]; di[i] = ti[K8 - 1 - i]; }

    shfl_merge8(d, di, 16);
    shfl_merge8(d, di, 8);
    shfl_merge8(d, di, 4);
    shfl_merge8(d, di, 2);
    shfl_merge8(d, di, 1);

    if (lane == 0) {
#pragma unroll
        for (int i = 0; i < K8; i++) { sv[wid * K8 + i] = d[i]; si[wid * K8 + i] = di[i]; }
    }
    __syncthreads();

    if (wid == 0) {
        int src = lane & 7;
#pragma unroll
        for (int i = 0; i < K8; i++) { d[i] = sv[src * K8 + i]; di[i] = si[src * K8 + i]; }
        shfl_merge8(d, di, 4);
        shfl_merge8(d, di, 2);
        shfl_merge8(d, di, 1);
        if (lane == 0) {
            float w[K8]; float s = 0.0f;
#pragma unroll
            for (int j = 0; j < K8; j++) { w[j] = expf(d[j] - d[0]); s += w[j]; }
            float inv = 1.0f / s;
#pragma unroll
            for (int j = 0; j < K8; j++) {
                g_rowW[row * K8 + j] = w[j] * inv;
                g_rowI[row * K8 + j] = di[j];
            }
        }
    }
}

// ---------------- column top-8: 8x batched loads (MLP=8) ----------------
__global__ void col_topk_part(const float* __restrict__ S) {
    const int c  = blockIdx.x * blockDim.x + threadIdx.x;
    const int ch = blockIdx.y;
    const int rows = BATCH / NCH;
    const int r0 = ch * rows;

    float tv[K8]; int ti[K8];
#pragma unroll
    for (int t = 0; t < K8; t++) { tv[t] = -1e30f; ti[t] = 0; }

    const float* p = S + (size_t)r0 * BATCH + c;
    for (int r = 0; r < rows; r += 8) {
        float vals[8];
#pragma unroll
        for (int e = 0; e < 8; e++) vals[e] = p[(size_t)(r + e) * BATCH];
        float m8 = vals[0];
#pragma unroll
        for (int e = 1; e < 8; e++) m8 = fmaxf(m8, vals[e]);
        if (m8 > tv[0]) {
#pragma unroll
            for (int e = 0; e < 8; e++) {
                float v = vals[e];
                if (v > tv[0]) {
                    tv[0] = v; ti[0] = r0 + r + e;
#pragma unroll
                    for (int q = 0; q < K8 - 1; q++) {
                        if (tv[q] > tv[q + 1]) {
                            float a = tv[q]; tv[q] = tv[q + 1]; tv[q + 1] = a;
                            int b = ti[q]; ti[q] = ti[q + 1]; ti[q + 1] = b;
                        }
                    }
                }
            }
        }
    }
    size_t base = ((size_t)ch * BATCH + c) * K8;
#pragma unroll
    for (int t = 0; t < K8; t++) { g_cpV[base + t] = tv[t]; g_cpI[base + t] = ti[t]; }
}

__global__ void col_merge_softmax() {
    const int c = blockIdx.x * blockDim.x + threadIdx.x;
    float tv[K8]; int ti[K8];
#pragma unroll
    for (int t = 0; t < K8; t++) { tv[t] = -1e30f; ti[t] = 0; }

    for (int ch = 0; ch < NCH; ch++) {
        size_t base = ((size_t)ch * BATCH + c) * K8;
#pragma unroll
        for (int t = 0; t < K8; t++) {
            float v = g_cpV[base + t];
            if (v > tv[0]) {
                int vi = g_cpI[base + t];
                tv[0] = v; ti[0] = vi;
#pragma unroll
                for (int q = 0; q < K8 - 1; q++) {
                    if (tv[q] > tv[q + 1]) {
                        float a = tv[q]; tv[q] = tv[q + 1]; tv[q + 1] = a;
                        int b = ti[q]; ti[q] = ti[q + 1]; ti[q + 1] = b;
                    }
                }
            }
        }
    }
    float mx = tv[K8 - 1];
    float w[K8]; float s = 0.0f;
#pragma unroll
    for (int t = 0; t < K8; t++) { w[t] = expf(tv[t] - mx); s += w[t]; }
    float inv = 1.0f / s;
#pragma unroll
    for (int t = 0; t < K8; t++) {
        g_colW[c * K8 + t] = w[t] * inv;
        g_colI[c * K8 + t] = ti[t];
    }
}

// ---------------- sparse message + residual + LayerNorm ----------------
__global__ void msg_ln_kernel(const float* __restrict__ X, const float* __restrict__ P,
                              const float* __restrict__ W, const int* __restrict__ IDX,
                              const float* __restrict__ gamma, const float* __restrict__ beta,
                              float* __restrict__ out) {
    __shared__ float sbuf[256];
    __shared__ float sw[K8];
    __shared__ int   sidx[K8];
    const int row = blockIdx.x, tid = threadIdx.x;
    if (tid < K8) { sw[tid] = W[row * K8 + tid]; sidx[tid] = IDX[row * K8 + tid]; }
    __syncthreads();

    float m0 = 0.0f, m1 = 0.0f;
#pragma unroll
    for (int j = 0; j < K8; j++) {
        const float* pr = P + (size_t)sidx[j] * DIM;
        float w = sw[j];
        m0 = fmaf(w, pr[tid], m0);
        m1 = fmaf(w, pr[tid + 256], m1);
    }
    float x0 = X[(size_t)row * DIM + tid]       + ALPHA * m0;
    float x1 = X[(size_t)row * DIM + tid + 256] + ALPHA * m1;

    sbuf[tid] = x0 + x1;
    __syncthreads();
    for (int s = 128; s > 0; s >>= 1) { if (tid < s) sbuf[tid] += sbuf[tid + s]; __syncthreads(); }
    float mu = sbuf[0] * (1.0f / DIM);
    __syncthreads();

    float d0 = x0 - mu, d1 = x1 - mu;
    sbuf[tid] = d0 * d0 + d1 * d1;
    __syncthreads();
    for (int s = 128; s > 0; s >>= 1) { if (tid < s) sbuf[tid] += sbuf[tid + s]; __syncthreads(); }
    float var = sbuf[0] * (1.0f / DIM);
    float rstd = rsqrtf(var + LN_EPS);

    out[(size_t)row * DIM + tid]       = d0 * rstd * gamma[tid]       + beta[tid];
    out[(size_t)row * DIM + tid + 256] = d1 * rstd * gamma[tid + 256] + beta[tid + 256];
}

// ---------------- launch: fully serial; row_topk placed 4th for ncu ----------------
extern "C" void kernel_launch(void* const* d_in, const int* in_sizes, int n_in,
                              void* d_out, int out_size) {
    const float* gI      = (const float*)d_in[0];
    const float* gT      = (const float*)d_in[1];
    const float* Wi      = (const float*)d_in[2];
    const float* Wt      = (const float*)d_in[3];
    const float* gamma_i = (const float*)d_in[4];
    const float* beta_i  = (const float*)d_in[5];
    const float* gamma_t = (const float*)d_in[6];
    const float* beta_t  = (const float*)d_in[7];

    float* out = (float*)d_out;
    float* gI2 = out;
    float* gT2 = out + (size_t)BATCH * DIM;
    float* S   = out + 2 * (size_t)BATCH * DIM;

    cudaFuncSetAttribute(gemm_mma, cudaFuncAttributeMaxDynamicSharedMemorySize, SMEM_DYN);

    void *p_gi_h, *p_gi_l, *p_gt_h, *p_gt_l;
    void *p_gIr_h, *p_gIr_l, *p_gTr_h, *p_gTr_l;
    void *p_Wi_h, *p_Wi_l, *p_Wt_h, *p_Wt_l;
    void *p_PT, *p_PI, *p_rowW, *p_rowI, *p_colW, *p_colI;
    cudaGetSymbolAddress(&p_gi_h, g_gi_h);   cudaGetSymbolAddress(&p_gi_l, g_gi_l);
    cudaGetSymbolAddress(&p_gt_h, g_gt_h);   cudaGetSymbolAddress(&p_gt_l, g_gt_l);
    cudaGetSymbolAddress(&p_gIr_h, g_gIr_h); cudaGetSymbolAddress(&p_gIr_l, g_gIr_l);
    cudaGetSymbolAddress(&p_gTr_h, g_gTr_h); cudaGetSymbolAddress(&p_gTr_l, g_gTr_l);
    cudaGetSymbolAddress(&p_Wi_h, g_Wi_h);   cudaGetSymbolAddress(&p_Wi_l, g_Wi_l);
    cudaGetSymbolAddress(&p_Wt_h, g_Wt_h);   cudaGetSymbolAddress(&p_Wt_l, g_Wt_l);
    cudaGetSymbolAddress(&p_PT, g_PT);       cudaGetSymbolAddress(&p_PI, g_PI);
    cudaGetSymbolAddress(&p_rowW, g_rowW);   cudaGetSymbolAddress(&p_rowI, g_rowI);
    cudaGetSymbolAddress(&p_colW, g_colW);   cudaGetSymbolAddress(&p_colI, g_colI);

    // (1)(2) normalize + split for S
    rownorm_split_kernel<<<BATCH, 256>>>(gI, (__nv_bfloat16*)p_gi_h, (__nv_bfloat16*)p_gi_l);
    rownorm_split_kernel<<<BATCH, 256>>>(gT, (__nv_bfloat16*)p_gt_h, (__nv_bfloat16*)p_gt_l);

    // (3) S = (gi @ gt^T) / tau   (needs only rownorm splits)
    gemm_mma<<<dim3(BATCH / BN, BATCH / BM), 256, SMEM_DYN>>>(
        (const __nv_bfloat16*)p_gi_h, (const __nv_bfloat16*)p_gi_l,
        (const __nv_bfloat16*)p_gt_h, (const __nv_bfloat16*)p_gt_l,
        S, BATCH, INV_TAU);

    // (4) row top-8 softmax   <-- 4th launch: profiled by ncu
    row_topk_kernel<<<BATCH, 256>>>(S);

    // (5)(6) column top-8 softmax
    col_topk_part<<<dim3(BATCH / 256, NCH), 256>>>(S);
    col_merge_softmax<<<BATCH / 256, 256>>>();

    // (7) fused split of gI, gT, Wi, Wt
    constexpr int NTOT = 2 * U_BIG + 2 * U_W;
    split_all_kernel<<<NTOT / 256, 256>>>(gI, gT, Wi, Wt);

    // (8)(9) projections
    gemm_mma<<<dim3(DIM / BN, BATCH / BM), 256, SMEM_DYN>>>(
        (const __nv_bfloat16*)p_gTr_h, (const __nv_bfloat16*)p_gTr_l,
        (const __nv_bfloat16*)p_Wt_h,  (const __nv_bfloat16*)p_Wt_l,
        (float*)p_PT, DIM, 1.0f);
    gemm_mma<<<dim3(DIM / BN, BATCH / BM), 256, SMEM_DYN>>>(
        (const __nv_bfloat16*)p_gIr_h, (const __nv_bfloat16*)p_gIr_l,
        (const __nv_bfloat16*)p_Wi_h,  (const __nv_bfloat16*)p_Wi_l,
        (float*)p_PI, DIM, 1.0f);

    // (10)(11) messages + residual + LayerNorm
    msg_ln_kernel<<<BATCH, 256>>>(gI, (const float*)p_PT, (const float*)p_rowW,
                                  (const int*)p_rowI, gamma_i, beta_i, gI2);
    msg_ln_kernel<<<BATCH, 256>>>(gT, (const float*)p_PI, (const float*)p_colW,
                                  (const int*)p_colI, gamma_t, beta_t, gT2);
}

// round 15
// speedup vs baseline: 1.2187x; 1.0806x over previous
#include <cuda_runtime.h>
#include <cuda_bf16.h>
#include <math.h>
#include <stdint.h>

// Problem constants
constexpr int BATCH = 8192;
constexpr int DIM   = 512;
constexpr int K8    = 8;
constexpr int NCH   = 16;
constexpr float INV_TAU = 5.0f;
constexpr float ALPHA   = 0.3f;
constexpr float LN_EPS  = 1e-5f;

// GEMM tiling (R8 proven): CTA 128x256, BK=64, double-buffered bulk-copy pipeline
constexpr int BM = 128, BN = 256, BK = 64;
constexpr int KCH = DIM / BK;
constexpr int BLKE = 128 * 64;
constexpr int BLKB = 16384;
constexpr int STAGE = 6 * BLKB;
constexpr int SMEM_DYN = 1024 + 2 * STAGE;

// ---------------- scratch ----------------
__device__ __nv_bfloat16 g_gi_h[BATCH * DIM], g_gi_l[BATCH * DIM];
__device__ __nv_bfloat16 g_gt_h[BATCH * DIM], g_gt_l[BATCH * DIM];
__device__ __nv_bfloat16 g_gIr_h[BATCH * DIM], g_gIr_l[BATCH * DIM];
__device__ __nv_bfloat16 g_gTr_h[BATCH * DIM], g_gTr_l[BATCH * DIM];
__device__ __nv_bfloat16 g_Wi_h[DIM * DIM], g_Wi_l[DIM * DIM];
__device__ __nv_bfloat16 g_Wt_h[DIM * DIM], g_Wt_l[DIM * DIM];
__device__ float g_PT[BATCH * DIM];
__device__ float g_PI[BATCH * DIM];
__device__ float g_rowW[BATCH * K8];
__device__ int   g_rowI[BATCH * K8];
__device__ float g_colW[BATCH * K8];
__device__ int   g_colI[BATCH * K8];
__device__ float g_cpV[NCH * BATCH * K8];
__device__ int   g_cpI[NCH * BATCH * K8];

// ---------------- PTX helpers ----------------
__device__ __forceinline__ uint32_t smem_u32(const void* p) {
    return (uint32_t)__cvta_generic_to_shared(p);
}
__device__ __forceinline__ void ldsm4(uint32_t* r, uint32_t a) {
    asm volatile("ldmatrix.sync.aligned.m8n8.x4.shared.b16 {%0,%1,%2,%3}, [%4];"
                 : "=r"(r[0]), "=r"(r[1]), "=r"(r[2]), "=r"(r[3]) : "r"(a));
}
__device__ __forceinline__ void mma_bf16(float* c, const uint32_t* a,
                                         uint32_t b0, uint32_t b1) {
    asm volatile("mma.sync.aligned.m16n8k16.row.col.f32.bf16.bf16.f32 "
                 "{%0,%1,%2,%3}, {%4,%5,%6,%7}, {%8,%9}, {%0,%1,%2,%3};"
                 : "+f"(c[0]), "+f"(c[1]), "+f"(c[2]), "+f"(c[3])
                 : "r"(a[0]), "r"(a[1]), "r"(a[2]), "r"(a[3]), "r"(b0), "r"(b1));
}
__device__ __forceinline__ void mbar_init(uint32_t a, uint32_t cnt) {
    asm volatile("mbarrier.init.shared.b64 [%0], %1;" :: "r"(a), "r"(cnt) : "memory");
}
__device__ __forceinline__ void mbar_expect(uint32_t a, uint32_t bytes) {
    asm volatile("mbarrier.arrive.expect_tx.shared.b64 _, [%0], %1;"
                 :: "r"(a), "r"(bytes) : "memory");
}
__device__ __forceinline__ void mbar_wait(uint32_t a, uint32_t parity) {
    uint32_t done;
    asm volatile("{\n\t.reg .pred p;\n\t"
                 "mbarrier.try_wait.parity.acquire.cta.shared::cta.b64 p, [%1], %2;\n\t"
                 "selp.b32 %0, 1, 0, p;\n\t}" : "=r"(done) : "r"(a), "r"(parity) : "memory");
    if (!done) {
        asm volatile("{\n\t.reg .pred P1;\n\t"
                     "W_%=:\n\t"
                     "mbarrier.try_wait.parity.acquire.cta.shared::cta.b64 P1, [%0], %1, 0x989680;\n\t"
                     "@P1 bra.uni D_%=;\n\t"
                     "bra.uni W_%=;\n\t"
                     "D_%=:\n\t}" :: "r"(a), "r"(parity) : "memory");
    }
}
__device__ __forceinline__ void bulk_cp(uint32_t dst, const void* src, uint32_t bytes,
                                        uint32_t mbar) {
    asm volatile("cp.async.bulk.shared::cta.global.mbarrier::complete_tx::bytes "
                 "[%0], [%1], %2, [%3];"
                 :: "r"(dst), "l"(__cvta_generic_to_global(src)), "r"(bytes), "r"(mbar)
                 : "memory");
}

// ---------------- split-bf16 GEMM on mma.sync (R8 proven, unchanged) ----------------
__global__ void __launch_bounds__(256, 1)
gemm_mma(const __nv_bfloat16* __restrict__ Ah, const __nv_bfloat16* __restrict__ Al,
         const __nv_bfloat16* __restrict__ Bh, const __nv_bfloat16* __restrict__ Bl,
         float* __restrict__ C, int ldc, float alpha)
{
    extern __shared__ char smem[];
    const uint32_t sb = smem_u32(smem);
    const uint32_t mb = sb;
    const uint32_t bufb = (sb + 1024u) & ~1023u;
    const int tid = threadIdx.x, wid = tid >> 5, lane = tid & 31;
    const int wm = wid >> 2, wn = wid & 3;
    const int bm = blockIdx.y * BM, bn = blockIdx.x * BN;
    const int g = lane >> 3, r8 = lane & 7;

    uint32_t abase[4], bbase[4];
#pragma unroll
    for (int i = 0; i < 4; i++) {
        int row = wm * 64 + i * 16 + r8 + (g & 1) * 8;
        abase[i] = (uint32_t)(row * 128);
    }
#pragma unroll
    for (int j = 0; j < 4; j++) {
        int row = wn * 64 + j * 16 + r8 + (g >> 1) * 8;
        bbase[j] = (uint32_t)((row & 127) * 128 + (row >> 7) * BLKB);
    }
    const uint32_t acsel = (uint32_t)((g >> 1) * 16);
    const uint32_t bcsel = (uint32_t)((g & 1) * 16);

    float acc[4][8][4];
#pragma unroll
    for (int i = 0; i < 4; i++)
#pragma unroll
        for (int j = 0; j < 8; j++)
#pragma unroll
            for (int q = 0; q < 4; q++) acc[i][j][q] = 0.0f;

    auto arm_load = [&](int s, int kc) {
        uint32_t mbar = mb + (uint32_t)s * 8;
        mbar_expect(mbar, STAGE);
        uint32_t st = bufb + (uint32_t)s * STAGE;
        size_t a  = ((size_t)((bm >> 7) * KCH + kc)) * BLKE;
        size_t b0 = ((size_t)((bn >> 7) * KCH + kc)) * BLKE;
        size_t b1 = ((size_t)(((bn >> 7) + 1) * KCH + kc)) * BLKE;
        bulk_cp(st,             Ah + a,  BLKB, mbar);
        bulk_cp(st + BLKB,      Al + a,  BLKB, mbar);
        bulk_cp(st + 2 * BLKB,  Bh + b0, BLKB, mbar);
        bulk_cp(st + 3 * BLKB,  Bh + b1, BLKB, mbar);
        bulk_cp(st + 4 * BLKB,  Bl + b0, BLKB, mbar);
        bulk_cp(st + 5 * BLKB,  Bl + b1, BLKB, mbar);
    };

    if (tid == 0) { mbar_init(mb, 1); mbar_init(mb + 8, 1); }
    __syncthreads();
    if (tid == 0) { arm_load(0, 0); arm_load(1, 1); }

    for (int t = 0; t < KCH; t++) {
        mbar_wait(mb + (uint32_t)(t & 1) * 8, (t >> 1) & 1);
        const uint32_t st = bufb + (uint32_t)(t & 1) * STAGE;

#pragma unroll
        for (int ks = 0; ks < 4; ks++) {
            const uint32_t ac = acsel + ks * 32;
            const uint32_t bc = bcsel + ks * 32;
            uint32_t Afr[4][4], Alf[4][4], Bhf[4][4], Blf[4][4];
#pragma unroll
            for (int i = 0; i < 4; i++) {
                uint32_t o = abase[i] + ac; o ^= (o >> 3) & 0x70;
                ldsm4(Afr[i], st + o);
            }
#pragma unroll
            for (int j = 0; j < 4; j++) {
                uint32_t o = bbase[j] + bc; o ^= (o >> 3) & 0x70;
                ldsm4(Bhf[j], st + 2 * BLKB + o);
            }
#pragma unroll
            for (int i = 0; i < 4; i++) {
                uint32_t o = abase[i] + ac; o ^= (o >> 3) & 0x70;
                ldsm4(Alf[i], st + BLKB + o);
            }
#pragma unroll
            for (int j = 0; j < 4; j++) {
                uint32_t o = bbase[j] + bc; o ^= (o >> 3) & 0x70;
                ldsm4(Blf[j], st + 4 * BLKB + o);
            }
#pragma unroll
            for (int i = 0; i < 4; i++)
#pragma unroll
                for (int j = 0; j < 4; j++) {
                    mma_bf16(acc[i][2 * j],     Afr[i], Bhf[j][0], Bhf[j][1]);
                    mma_bf16(acc[i][2 * j + 1], Afr[i], Bhf[j][2], Bhf[j][3]);
                }
#pragma unroll
            for (int i = 0; i < 4; i++)
#pragma unroll
                for (int j = 0; j < 4; j++) {
                    mma_bf16(acc[i][2 * j],     Alf[i], Bhf[j][0], Bhf[j][1]);
                    mma_bf16(acc[i][2 * j + 1], Alf[i], Bhf[j][2], Bhf[j][3]);
                }
#pragma unroll
            for (int i = 0; i < 4; i++)
#pragma unroll
                for (int j = 0; j < 4; j++) {
                    mma_bf16(acc[i][2 * j],     Afr[i], Blf[j][0], Blf[j][1]);
                    mma_bf16(acc[i][2 * j + 1], Afr[i], Blf[j][2], Blf[j][3]);
                }
        }

        __syncthreads();
        if (t + 2 < KCH && tid == 0) arm_load(t & 1, t + 2);
    }

    const int row0 = bm + wm * 64 + (lane >> 2);
    const int col0 = bn + wn * 64 + (lane & 3) * 2;
#pragma unroll
    for (int i = 0; i < 4; i++) {
#pragma unroll
        for (int j = 0; j < 8; j++) {
            int r = row0 + i * 16, cc = col0 + j * 8;
            float2 v0 = make_float2(acc[i][j][0] * alpha, acc[i][j][1] * alpha);
            float2 v1 = make_float2(acc[i][j][2] * alpha, acc[i][j][3] * alpha);
            *(float2*)&C[(size_t)r * ldc + cc]       = v0;
            *(float2*)&C[(size_t)(r + 8) * ldc + cc] = v1;
        }
    }
}

// ---------------- conversions ----------------
__device__ __forceinline__ void split_bf16(float x, __nv_bfloat16& h, __nv_bfloat16& l) {
    h = __float2bfloat16_rn(x);
    l = __float2bfloat16_rn(x - __bfloat162float(h));
}

__device__ __forceinline__ size_t blk_idx(int row, int u) {
    int rb = row >> 7, kc = u >> 3;
    uint32_t off = (uint32_t)((row & 127) * 128 + (u & 7) * 16);
    off ^= (off >> 3) & 0x70;
    return ((size_t)(rb * KCH + kc)) * BLKE + (off >> 1);
}

__global__ void rownorm_split_kernel(const float* __restrict__ X,
                                     __nv_bfloat16* __restrict__ Yh,
                                     __nv_bfloat16* __restrict__ Yl) {
    __shared__ float sbuf[256];
    __shared__ float rowv[512];
    int row = blockIdx.x, tid = threadIdx.x;
    const float* x = X + (size_t)row * DIM;
    float v0 = x[tid], v1 = x[tid + 256];
    rowv[tid] = v0; rowv[tid + 256] = v1;
    sbuf[tid] = v0 * v0 + v1 * v1;
    __syncthreads();
    for (int s = 128; s > 0; s >>= 1) {
        if (tid < s) sbuf[tid] += sbuf[tid + s];
        __syncthreads();
    }
    float inv = 1.0f / fmaxf(sqrtf(sbuf[0]), 1e-12f);
    if (tid < 128) {
        int u = tid & 63;
        bool hi = tid < 64;
        __nv_bfloat16 out[8];
#pragma unroll
        for (int e = 0; e < 8; e++) {
            float v = rowv[u * 8 + e] * inv;
            __nv_bfloat16 h, l;
            split_bf16(v, h, l);
            out[e] = hi ? h : l;
        }
        size_t idx = blk_idx(row, u);
        *(uint4*)((hi ? Yh : Yl) + idx) = *(uint4*)out;
    }
}

constexpr int NBIG = BATCH * DIM;
constexpr int NW   = DIM * DIM;
constexpr int U_BIG = NBIG / 8;
constexpr int U_W   = NW / 8;
__global__ void split_all_kernel(const float* __restrict__ gI, const float* __restrict__ gT,
                                 const float* __restrict__ Wi, const float* __restrict__ Wt) {
    int gidx = blockIdx.x * blockDim.x + threadIdx.x;
    const float* src; __nv_bfloat16 *H, *L; int unit;
    if (gidx < U_BIG)                { src = gI; H = g_gIr_h; L = g_gIr_l; unit = gidx; }
    else if (gidx < 2 * U_BIG)       { src = gT; H = g_gTr_h; L = g_gTr_l; unit = gidx - U_BIG; }
    else if (gidx < 2 * U_BIG + U_W) { src = Wi; H = g_Wi_h;  L = g_Wi_l;  unit = gidx - 2 * U_BIG; }
    else                             { src = Wt; H = g_Wt_h;  L = g_Wt_l;  unit = gidx - 2 * U_BIG - U_W; }
    int row = unit >> 6, u = unit & 63;
    const float4* s4 = (const float4*)(src + (size_t)row * DIM + u * 8);
    float4 a = s4[0], b = s4[1];
    float vals[8] = {a.x, a.y, a.z, a.w, b.x, b.y, b.z, b.w};
    __nv_bfloat16 h[8], l[8];
#pragma unroll
    for (int e = 0; e < 8; e++) split_bf16(vals[e], h[e], l[e]);
    size_t idx = blk_idx(row, u);
    *(uint4*)(H + idx) = *(uint4*)h;
    *(uint4*)(L + idx) = *(uint4*)l;
}

// ---------------- value-only merge network helpers ----------------
__device__ __forceinline__ void cev(float* d, int i, int j) {
    float hi = fmaxf(d[i], d[j]);
    float lo = fminf(d[i], d[j]);
    d[i] = hi; d[j] = lo;
}
__device__ __forceinline__ void vresort8(float* d) {
    cev(d, 0, 4); cev(d, 1, 5); cev(d, 2, 6); cev(d, 3, 7);
    cev(d, 0, 2); cev(d, 1, 3); cev(d, 4, 6); cev(d, 5, 7);
    cev(d, 0, 1); cev(d, 2, 3); cev(d, 4, 5); cev(d, 6, 7);
}
__device__ __forceinline__ void vmerge8(float* d, int off) {
    float pd[K8];
#pragma unroll
    for (int i = 0; i < K8; i++) pd[i] = __shfl_xor_sync(0xffffffffu, d[i], off);
#pragma unroll
    for (int i = 0; i < K8; i++) d[i] = fmaxf(d[i], pd[K8 - 1 - i]);
    vresort8(d);
}

// ---------------- row top-8 + softmax: value-only merge + candidate extraction ----------------
__global__ void row_topk_kernel(const float* __restrict__ S) {
    __shared__ float swv[8 * K8];
    __shared__ float s_v8;
    __shared__ float cv[64];
    __shared__ int   ci[64];
    __shared__ int   s_cnt;
    const int row = blockIdx.x, tid = threadIdx.x;
    const int wid = tid >> 5, lane = tid & 31;
    const float4* Sr4 = (const float4*)(S + (size_t)row * BATCH);

    if (tid == 0) s_cnt = 0;

    // hoist all 8 float4 loads; values stay live in registers for extraction
    float4 v[8];
#pragma unroll
    for (int it = 0; it < 8; it++) v[it] = Sr4[it * 256 + tid];

    // value-only per-thread top-8 (tv ascending: tv[0] = current 8th-largest)
    float tv[K8];
#pragma unroll
    for (int t = 0; t < K8; t++) tv[t] = -1e30f;

#pragma unroll
    for (int it = 0; it < 8; it++) {
        float m4 = fmaxf(fmaxf(v[it].x, v[it].y), fmaxf(v[it].z, v[it].w));
        if (m4 > tv[0]) {
            float vals[4] = {v[it].x, v[it].y, v[it].z, v[it].w};
#pragma unroll
            for (int e = 0; e < 4; e++) {
                float x = vals[e];
                if (x > tv[0]) {
                    tv[0] = x;
#pragma unroll
                    for (int q = 0; q < K8 - 1; q++) {
                        float lo = fminf(tv[q], tv[q + 1]);
                        float hi = fmaxf(tv[q], tv[q + 1]);
                        tv[q] = lo; tv[q + 1] = hi;
                    }
                }
            }
        }
    }

    // descending copy + value-only butterfly merge (5 rounds)
    float d[K8];
#pragma unroll
    for (int i = 0; i < K8; i++) d[i] = tv[K8 - 1 - i];
    vmerge8(d, 16); vmerge8(d, 8); vmerge8(d, 4); vmerge8(d, 2); vmerge8(d, 1);

    if (lane == 0) {
#pragma unroll
        for (int i = 0; i < K8; i++) swv[wid * K8 + i] = d[i];
    }
    __syncthreads();

    // warp 0 merges 8 warp lists (values only) -> v8 = block's 8th-largest
    if (wid == 0) {
        int src = lane & 7;
#pragma unroll
        for (int i = 0; i < K8; i++) d[i] = swv[src * K8 + i];
        vmerge8(d, 4); vmerge8(d, 2); vmerge8(d, 1);
        if (lane == 0) s_v8 = d[K8 - 1];
    }
    __syncthreads();

    // extraction: emit (value, index) for all elements >= v8 (>= 8 always)
    const float v8 = s_v8;
#pragma unroll
    for (int it = 0; it < 8; it++) {
        float m4 = fmaxf(fmaxf(v[it].x, v[it].y), fmaxf(v[it].z, v[it].w));
        if (m4 >= v8) {
            float vals[4] = {v[it].x, v[it].y, v[it].z, v[it].w};
            int base = (it * 256 + tid) * 4;
#pragma unroll
            for (int e = 0; e < 4; e++) {
                if (vals[e] >= v8) {
                    int p = atomicAdd(&s_cnt, 1);
                    if (p < 64) { cv[p] = vals[e]; ci[p] = base + e; }
                }
            }
        }
    }
    __syncthreads();

    // thread 0: select top-8 (tie -> smaller index), softmax, write
    if (tid == 0) {
        int n = s_cnt < 64 ? s_cnt : 64;
        float outv[K8]; int outi[K8];
#pragma unroll
        for (int sel = 0; sel < K8; sel++) {
            float m = -1e30f; int mi = 0x7fffffff; int mk = 0;
            for (int k = 0; k < n; k++) {
                float x = cv[k];
                if (x > m || (x == m && ci[k] < mi)) { m = x; mi = ci[k]; mk = k; }
            }
            outv[sel] = m; outi[sel] = mi;
            cv[mk] = -1e30f;
        }
        float w[K8]; float s = 0.0f;
#pragma unroll
        for (int j = 0; j < K8; j++) { w[j] = expf(outv[j] - outv[0]); s += w[j]; }
        float inv = 1.0f / s;
#pragma unroll
        for (int j = 0; j < K8; j++) {
            g_rowW[row * K8 + j] = w[j] * inv;
            g_rowI[row * K8 + j] = outi[j];
        }
    }
}

// ---------------- column top-8: 8x batched loads ----------------
__global__ void col_topk_part(const float* __restrict__ S) {
    const int c  = blockIdx.x * blockDim.x + threadIdx.x;
    const int ch = blockIdx.y;
    const int rows = BATCH / NCH;
    const int r0 = ch * rows;

    float tv[K8]; int ti[K8];
#pragma unroll
    for (int t = 0; t < K8; t++) { tv[t] = -1e30f; ti[t] = 0; }

    const float* p = S + (size_t)r0 * BATCH + c;
    for (int r = 0; r < rows; r += 8) {
        float vals[8];
#pragma unroll
        for (int e = 0; e < 8; e++) vals[e] = p[(size_t)(r + e) * BATCH];
        float m8 = vals[0];
#pragma unroll
        for (int e = 1; e < 8; e++) m8 = fmaxf(m8, vals[e]);
        if (m8 > tv[0]) {
#pragma unroll
            for (int e = 0; e < 8; e++) {
                float v = vals[e];
                if (v > tv[0]) {
                    tv[0] = v; ti[0] = r0 + r + e;
#pragma unroll
                    for (int q = 0; q < K8 - 1; q++) {
                        if (tv[q] > tv[q + 1]) {
                            float a = tv[q]; tv[q] = tv[q + 1]; tv[q + 1] = a;
                            int b = ti[q]; ti[q] = ti[q + 1]; ti[q + 1] = b;
                        }
                    }
                }
            }
        }
    }
    size_t base = ((size_t)ch * BATCH + c) * K8;
#pragma unroll
    for (int t = 0; t < K8; t++) { g_cpV[base + t] = tv[t]; g_cpI[base + t] = ti[t]; }
}

__global__ void col_merge_softmax() {
    const int c = blockIdx.x * blockDim.x + threadIdx.x;
    float tv[K8]; int ti[K8];
#pragma unroll
    for (int t = 0; t < K8; t++) { tv[t] = -1e30f; ti[t] = 0; }

    for (int ch = 0; ch < NCH; ch++) {
        size_t base = ((size_t)ch * BATCH + c) * K8;
#pragma unroll
        for (int t = 0; t < K8; t++) {
            float v = g_cpV[base + t];
            if (v > tv[0]) {
                int vi = g_cpI[base + t];
                tv[0] = v; ti[0] = vi;
#pragma unroll
                for (int q = 0; q < K8 - 1; q++) {
                    if (tv[q] > tv[q + 1]) {
                        float a = tv[q]; tv[q] = tv[q + 1]; tv[q + 1] = a;
                        int b = ti[q]; ti[q] = ti[q + 1]; ti[q + 1] = b;
                    }
                }
            }
        }
    }
    float mx = tv[K8 - 1];
    float w[K8]; float s = 0.0f;
#pragma unroll
    for (int t = 0; t < K8; t++) { w[t] = expf(tv[t] - mx); s += w[t]; }
    float inv = 1.0f / s;
#pragma unroll
    for (int t = 0; t < K8; t++) {
        g_colW[c * K8 + t] = w[t] * inv;
        g_colI[c * K8 + t] = ti[t];
    }
}

// ---------------- sparse message + residual + LayerNorm ----------------
__global__ void msg_ln_kernel(const float* __restrict__ X, const float* __restrict__ P,
                              const float* __restrict__ W, const int* __restrict__ IDX,
                              const float* __restrict__ gamma, const float* __restrict__ beta,
                              float* __restrict__ out) {
    __shared__ float sbuf[256];
    __shared__ float sw[K8];
    __shared__ int   sidx[K8];
    const int row = blockIdx.x, tid = threadIdx.x;
    if (tid < K8) { sw[tid] = W[row * K8 + tid]; sidx[tid] = IDX[row * K8 + tid]; }
    __syncthreads();

    float m0 = 0.0f, m1 = 0.0f;
#pragma unroll
    for (int j = 0; j < K8; j++) {
        const float* pr = P + (size_t)sidx[j] * DIM;
        float w = sw[j];
        m0 = fmaf(w, pr[tid], m0);
        m1 = fmaf(w, pr[tid + 256], m1);
    }
    float x0 = X[(size_t)row * DIM + tid]       + ALPHA * m0;
    float x1 = X[(size_t)row * DIM + tid + 256] + ALPHA * m1;

    sbuf[tid] = x0 + x1;
    __syncthreads();
    for (int s = 128; s > 0; s >>= 1) { if (tid < s) sbuf[tid] += sbuf[tid + s]; __syncthreads(); }
    float mu = sbuf[0] * (1.0f / DIM);
    __syncthreads();

    float d0 = x0 - mu, d1 = x1 - mu;
    sbuf[tid] = d0 * d0 + d1 * d1;
    __syncthreads();
    for (int s = 128; s > 0; s >>= 1) { if (tid < s) sbuf[tid] += sbuf[tid + s]; __syncthreads(); }
    float var = sbuf[0] * (1.0f / DIM);
    float rstd = rsqrtf(var + LN_EPS);

    out[(size_t)row * DIM + tid]       = d0 * rstd * gamma[tid]       + beta[tid];
    out[(size_t)row * DIM + tid + 256] = d1 * rstd * gamma[tid + 256] + beta[tid + 256];
}

// ---------------- launch: fully serial; row_topk 4th for ncu ----------------
extern "C" void kernel_launch(void* const* d_in, const int* in_sizes, int n_in,
                              void* d_out, int out_size) {
    const float* gI      = (const float*)d_in[0];
    const float* gT      = (const float*)d_in[1];
    const float* Wi      = (const float*)d_in[2];
    const float* Wt      = (const float*)d_in[3];
    const float* gamma_i = (const float*)d_in[4];
    const float* beta_i  = (const float*)d_in[5];
    const float* gamma_t = (const float*)d_in[6];
    const float* beta_t  = (const float*)d_in[7];

    float* out = (float*)d_out;
    float* gI2 = out;
    float* gT2 = out + (size_t)BATCH * DIM;
    float* S   = out + 2 * (size_t)BATCH * DIM;

    cudaFuncSetAttribute(gemm_mma, cudaFuncAttributeMaxDynamicSharedMemorySize, SMEM_DYN);

    void *p_gi_h, *p_gi_l, *p_gt_h, *p_gt_l;
    void *p_gIr_h, *p_gIr_l, *p_gTr_h, *p_gTr_l;
    void *p_Wi_h, *p_Wi_l, *p_Wt_h, *p_Wt_l;
    void *p_PT, *p_PI, *p_rowW, *p_rowI, *p_colW, *p_colI;
    cudaGetSymbolAddress(&p_gi_h, g_gi_h);   cudaGetSymbolAddress(&p_gi_l, g_gi_l);
    cudaGetSymbolAddress(&p_gt_h, g_gt_h);   cudaGetSymbolAddress(&p_gt_l, g_gt_l);
    cudaGetSymbolAddress(&p_gIr_h, g_gIr_h); cudaGetSymbolAddress(&p_gIr_l, g_gIr_l);
    cudaGetSymbolAddress(&p_gTr_h, g_gTr_h); cudaGetSymbolAddress(&p_gTr_l, g_gTr_l);
    cudaGetSymbolAddress(&p_Wi_h, g_Wi_h);   cudaGetSymbolAddress(&p_Wi_l, g_Wi_l);
    cudaGetSymbolAddress(&p_Wt_h, g_Wt_h);   cudaGetSymbolAddress(&p_Wt_l, g_Wt_l);
    cudaGetSymbolAddress(&p_PT, g_PT);       cudaGetSymbolAddress(&p_PI, g_PI);
    cudaGetSymbolAddress(&p_rowW, g_rowW);   cudaGetSymbolAddress(&p_rowI, g_rowI);
    cudaGetSymbolAddress(&p_colW, g_colW);   cudaGetSymbolAddress(&p_colI, g_colI);

    // (1)(2) normalize + split for S
    rownorm_split_kernel<<<BATCH, 256>>>(gI, (__nv_bfloat16*)p_gi_h, (__nv_bfloat16*)p_gi_l);
    rownorm_split_kernel<<<BATCH, 256>>>(gT, (__nv_bfloat16*)p_gt_h, (__nv_bfloat16*)p_gt_l);

    // (3) S = (gi @ gt^T) / tau
    gemm_mma<<<dim3(BATCH / BN, BATCH / BM), 256, SMEM_DYN>>>(
        (const __nv_bfloat16*)p_gi_h, (const __nv_bfloat16*)p_gi_l,
        (const __nv_bfloat16*)p_gt_h, (const __nv_bfloat16*)p_gt_l,
        S, BATCH, INV_TAU);

    // (4) row top-8 softmax   <-- 4th launch: profiled by ncu
    row_topk_kernel<<<BATCH, 256>>>(S);

    // (5)(6) column top-8 softmax
    col_topk_part<<<dim3(BATCH / 256, NCH), 256>>>(S);
    col_merge_softmax<<<BATCH / 256, 256>>>();

    // (7) fused split of gI, gT, Wi, Wt
    constexpr int NTOT = 2 * U_BIG + 2 * U_W;
    split_all_kernel<<<NTOT / 256, 256>>>(gI, gT, Wi, Wt);

    // (8)(9) projections
    gemm_mma<<<dim3(DIM / BN, BATCH / BM), 256, SMEM_DYN>>>(
        (const __nv_bfloat16*)p_gTr_h, (const __nv_bfloat16*)p_gTr_l,
        (const __nv_bfloat16*)p_Wt_h,  (const __nv_bfloat16*)p_Wt_l,
        (float*)p_PT, DIM, 1.0f);
    gemm_mma<<<dim3(DIM / BN, BATCH / BM), 256, SMEM_DYN>>>(
        (const __nv_bfloat16*)p_gIr_h, (const __nv_bfloat16*)p_gIr_l,
        (const __nv_bfloat16*)p_Wi_h,  (const __nv_bfloat16*)p_Wi_l,
        (float*)p_PI, DIM, 1.0f);

    // (10)(11) messages + residual + LayerNorm
    msg_ln_kernel<<<BATCH, 256>>>(gI, (const float*)p_PT, (const float*)p_rowW,
                                  (const int*)p_rowI, gamma_i, beta_i, gI2);
    msg_ln_kernel<<<BATCH, 256>>>(gT, (const float*)p_PI, (const float*)p_colW,
                                  (const int*)p_colI, gamma_t, beta_t, gT2);
}

// round 16
// speedup vs baseline: 1.2588x; 1.0330x over previous
#include <cuda_runtime.h>
#include <cuda_bf16.h>
#include <math.h>
#include <stdint.h>

// Problem constants
constexpr int BATCH = 8192;
constexpr int DIM   = 512;
constexpr int K8    = 8;
constexpr int NCH   = 16;
constexpr float INV_TAU = 5.0f;
constexpr float ALPHA   = 0.3f;
constexpr float LN_EPS  = 1e-5f;

// GEMM tiling (R8 proven): CTA 128x256, BK=64, double-buffered bulk-copy pipeline
constexpr int BM = 128, BN = 256, BK = 64;
constexpr int KCH = DIM / BK;
constexpr int BLKE = 128 * 64;
constexpr int BLKB = 16384;
constexpr int STAGE = 6 * BLKB;
constexpr int SMEM_DYN = 1024 + 2 * STAGE;

// ---------------- scratch ----------------
__device__ __nv_bfloat16 g_gi_h[BATCH * DIM], g_gi_l[BATCH * DIM];
__device__ __nv_bfloat16 g_gt_h[BATCH * DIM], g_gt_l[BATCH * DIM];
__device__ __nv_bfloat16 g_gIr_h[BATCH * DIM], g_gIr_l[BATCH * DIM];
__device__ __nv_bfloat16 g_gTr_h[BATCH * DIM], g_gTr_l[BATCH * DIM];
__device__ __nv_bfloat16 g_Wi_h[DIM * DIM], g_Wi_l[DIM * DIM];
__device__ __nv_bfloat16 g_Wt_h[DIM * DIM], g_Wt_l[DIM * DIM];
__device__ float g_PT[BATCH * DIM];
__device__ float g_PI[BATCH * DIM];
__device__ float g_rowW[BATCH * K8];
__device__ int   g_rowI[BATCH * K8];
__device__ float g_colW[BATCH * K8];
__device__ int   g_colI[BATCH * K8];
__device__ float g_cpV[NCH * BATCH * K8];
__device__ int   g_cpI[NCH * BATCH * K8];

// ---------------- PTX helpers ----------------
__device__ __forceinline__ uint32_t smem_u32(const void* p) {
    return (uint32_t)__cvta_generic_to_shared(p);
}
__device__ __forceinline__ void ldsm4(uint32_t* r, uint32_t a) {
    asm volatile("ldmatrix.sync.aligned.m8n8.x4.shared.b16 {%0,%1,%2,%3}, [%4];"
                 : "=r"(r[0]), "=r"(r[1]), "=r"(r[2]), "=r"(r[3]) : "r"(a));
}
__device__ __forceinline__ void mma_bf16(float* c, const uint32_t* a,
                                         uint32_t b0, uint32_t b1) {
    asm volatile("mma.sync.aligned.m16n8k16.row.col.f32.bf16.bf16.f32 "
                 "{%0,%1,%2,%3}, {%4,%5,%6,%7}, {%8,%9}, {%0,%1,%2,%3};"
                 : "+f"(c[0]), "+f"(c[1]), "+f"(c[2]), "+f"(c[3])
                 : "r"(a[0]), "r"(a[1]), "r"(a[2]), "r"(a[3]), "r"(b0), "r"(b1));
}
__device__ __forceinline__ void mbar_init(uint32_t a, uint32_t cnt) {
    asm volatile("mbarrier.init.shared.b64 [%0], %1;" :: "r"(a), "r"(cnt) : "memory");
}
__device__ __forceinline__ void mbar_expect(uint32_t a, uint32_t bytes) {
    asm volatile("mbarrier.arrive.expect_tx.shared.b64 _, [%0], %1;"
                 :: "r"(a), "r"(bytes) : "memory");
}
__device__ __forceinline__ void mbar_arrive(uint32_t a) {
    asm volatile("mbarrier.arrive.release.cta.shared::cta.b64 _, [%0];" :: "r"(a) : "memory");
}
__device__ __forceinline__ void mbar_wait(uint32_t a, uint32_t parity) {
    uint32_t done;
    asm volatile("{\n\t.reg .pred p;\n\t"
                 "mbarrier.try_wait.parity.acquire.cta.shared::cta.b64 p, [%1], %2;\n\t"
                 "selp.b32 %0, 1, 0, p;\n\t}" : "=r"(done) : "r"(a), "r"(parity) : "memory");
    if (!done) {
        asm volatile("{\n\t.reg .pred P1;\n\t"
                     "W_%=:\n\t"
                     "mbarrier.try_wait.parity.acquire.cta.shared::cta.b64 P1, [%0], %1, 0x989680;\n\t"
                     "@P1 bra.uni D_%=;\n\t"
                     "bra.uni W_%=;\n\t"
                     "D_%=:\n\t}" :: "r"(a), "r"(parity) : "memory");
    }
}
__device__ __forceinline__ void bulk_cp(uint32_t dst, const void* src, uint32_t bytes,
                                        uint32_t mbar) {
    asm volatile("cp.async.bulk.shared::cta.global.mbarrier::complete_tx::bytes "
                 "[%0], [%1], %2, [%3];"
                 :: "r"(dst), "l"(__cvta_generic_to_global(src)), "r"(bytes), "r"(mbar)
                 : "memory");
}

// ---------------- split-bf16 GEMM on mma.sync: empty-mbarrier pipeline ----------------
__global__ void __launch_bounds__(256, 1)
gemm_mma(const __nv_bfloat16* __restrict__ Ah, const __nv_bfloat16* __restrict__ Al,
         const __nv_bfloat16* __restrict__ Bh, const __nv_bfloat16* __restrict__ Bl,
         float* __restrict__ C, int ldc, float alpha)
{
    extern __shared__ char smem[];
    const uint32_t sb = smem_u32(smem);
    const uint32_t mb  = sb;        // full barriers: sb+0, sb+8
    const uint32_t emb = sb + 16;   // empty barriers: sb+16, sb+24
    const uint32_t bufb = (sb + 1024u) & ~1023u;
    const int tid = threadIdx.x, wid = tid >> 5, lane = tid & 31;
    const int wm = wid >> 2, wn = wid & 3;
    const int bm = blockIdx.y * BM, bn = blockIdx.x * BN;
    const int g = lane >> 3, r8 = lane & 7;

    uint32_t abase[4], bbase[4];
#pragma unroll
    for (int i = 0; i < 4; i++) {
        int row = wm * 64 + i * 16 + r8 + (g & 1) * 8;
        abase[i] = (uint32_t)(row * 128);
    }
#pragma unroll
    for (int j = 0; j < 4; j++) {
        int row = wn * 64 + j * 16 + r8 + (g >> 1) * 8;
        bbase[j] = (uint32_t)((row & 127) * 128 + (row >> 7) * BLKB);
    }
    const uint32_t acsel = (uint32_t)((g >> 1) * 16);
    const uint32_t bcsel = (uint32_t)((g & 1) * 16);

    float acc[4][8][4];
#pragma unroll
    for (int i = 0; i < 4; i++)
#pragma unroll
        for (int j = 0; j < 8; j++)
#pragma unroll
            for (int q = 0; q < 4; q++) acc[i][j][q] = 0.0f;

    auto arm_load = [&](int s, int kc) {
        uint32_t mbar = mb + (uint32_t)s * 8;
        mbar_expect(mbar, STAGE);
        uint32_t st = bufb + (uint32_t)s * STAGE;
        size_t a  = ((size_t)((bm >> 7) * KCH + kc)) * BLKE;
        size_t b0 = ((size_t)((bn >> 7) * KCH + kc)) * BLKE;
        size_t b1 = ((size_t)(((bn >> 7) + 1) * KCH + kc)) * BLKE;
        bulk_cp(st,             Ah + a,  BLKB, mbar);
        bulk_cp(st + BLKB,      Al + a,  BLKB, mbar);
        bulk_cp(st + 2 * BLKB,  Bh + b0, BLKB, mbar);
        bulk_cp(st + 3 * BLKB,  Bh + b1, BLKB, mbar);
        bulk_cp(st + 4 * BLKB,  Bl + b0, BLKB, mbar);
        bulk_cp(st + 5 * BLKB,  Bl + b1, BLKB, mbar);
    };

    if (tid == 0) {
        mbar_init(mb, 1);       mbar_init(mb + 8, 1);      // full (tx-based)
        mbar_init(emb, 256);    mbar_init(emb + 8, 256);   // empty (all threads)
    }
    __syncthreads();
    if (tid == 0) { arm_load(0, 0); arm_load(1, 1); }

    for (int t = 0; t < KCH; t++) {
        const int s = t & 1;
        mbar_wait(mb + (uint32_t)s * 8, (t >> 1) & 1);
        const uint32_t st = bufb + (uint32_t)s * STAGE;

#pragma unroll
        for (int ks = 0; ks < 4; ks++) {
            const uint32_t ac = acsel + ks * 32;
            const uint32_t bc = bcsel + ks * 32;
            uint32_t Afr[4][4], Alf[4][4], Bhf[4][4], Blf[4][4];
#pragma unroll
            for (int i = 0; i < 4; i++) {
                uint32_t o = abase[i] + ac; o ^= (o >> 3) & 0x70;
                ldsm4(Afr[i], st + o);
            }
#pragma unroll
            for (int j = 0; j < 4; j++) {
                uint32_t o = bbase[j] + bc; o ^= (o >> 3) & 0x70;
                ldsm4(Bhf[j], st + 2 * BLKB + o);
            }
#pragma unroll
            for (int i = 0; i < 4; i++) {
                uint32_t o = abase[i] + ac; o ^= (o >> 3) & 0x70;
                ldsm4(Alf[i], st + BLKB + o);
            }
#pragma unroll
            for (int j = 0; j < 4; j++) {
                uint32_t o = bbase[j] + bc; o ^= (o >> 3) & 0x70;
                ldsm4(Blf[j], st + 4 * BLKB + o);
            }
#pragma unroll
            for (int i = 0; i < 4; i++)
#pragma unroll
                for (int j = 0; j < 4; j++) {
                    mma_bf16(acc[i][2 * j],     Afr[i], Bhf[j][0], Bhf[j][1]);
                    mma_bf16(acc[i][2 * j + 1], Afr[i], Bhf[j][2], Bhf[j][3]);
                }
#pragma unroll
            for (int i = 0; i < 4; i++)
#pragma unroll
                for (int j = 0; j < 4; j++) {
                    mma_bf16(acc[i][2 * j],     Alf[i], Bhf[j][0], Bhf[j][1]);
                    mma_bf16(acc[i][2 * j + 1], Alf[i], Bhf[j][2], Bhf[j][3]);
                }
#pragma unroll
            for (int i = 0; i < 4; i++)
#pragma unroll
                for (int j = 0; j < 4; j++) {
                    mma_bf16(acc[i][2 * j],     Afr[i], Blf[j][0], Blf[j][1]);
                    mma_bf16(acc[i][2 * j + 1], Afr[i], Blf[j][2], Blf[j][3]);
                }
        }

        // producer/consumer recycle: no block barrier
        if (t + 2 < KCH) {
            mbar_arrive(emb + (uint32_t)s * 8);
            if (tid == 0) {
                mbar_wait(emb + (uint32_t)s * 8, (t >> 1) & 1);
                arm_load(s, t + 2);
            }
        }
    }

    const int row0 = bm + wm * 64 + (lane >> 2);
    const int col0 = bn + wn * 64 + (lane & 3) * 2;
#pragma unroll
    for (int i = 0; i < 4; i++) {
#pragma unroll
        for (int j = 0; j < 8; j++) {
            int r = row0 + i * 16, cc = col0 + j * 8;
            float2 v0 = make_float2(acc[i][j][0] * alpha, acc[i][j][1] * alpha);
            float2 v1 = make_float2(acc[i][j][2] * alpha, acc[i][j][3] * alpha);
            *(float2*)&C[(size_t)r * ldc + cc]       = v0;
            *(float2*)&C[(size_t)(r + 8) * ldc + cc] = v1;
        }
    }
}

// ---------------- conversions ----------------
__device__ __forceinline__ void split_bf16(float x, __nv_bfloat16& h, __nv_bfloat16& l) {
    h = __float2bfloat16_rn(x);
    l = __float2bfloat16_rn(x - __bfloat162float(h));
}

__device__ __forceinline__ size_t blk_idx(int row, int u) {
    int rb = row >> 7, kc = u >> 3;
    uint32_t off = (uint32_t)((row & 127) * 128 + (u & 7) * 16);
    off ^= (off >> 3) & 0x70;
    return ((size_t)(rb * KCH + kc)) * BLKE + (off >> 1);
}

__global__ void rownorm_split_kernel(const float* __restrict__ X,
                                     __nv_bfloat16* __restrict__ Yh,
                                     __nv_bfloat16* __restrict__ Yl) {
    __shared__ float sbuf[256];
    __shared__ float rowv[512];
    int row = blockIdx.x, tid = threadIdx.x;
    const float* x = X + (size_t)row * DIM;
    float v0 = x[tid], v1 = x[tid + 256];
    rowv[tid] = v0; rowv[tid + 256] = v1;
    sbuf[tid] = v0 * v0 + v1 * v1;
    __syncthreads();
    for (int s = 128; s > 0; s >>= 1) {
        if (tid < s) sbuf[tid] += sbuf[tid + s];
        __syncthreads();
    }
    float inv = 1.0f / fmaxf(sqrtf(sbuf[0]), 1e-12f);
    if (tid < 128) {
        int u = tid & 63;
        bool hi = tid < 64;
        __nv_bfloat16 out[8];
#pragma unroll
        for (int e = 0; e < 8; e++) {
            float v = rowv[u * 8 + e] * inv;
            __nv_bfloat16 h, l;
            split_bf16(v, h, l);
            out[e] = hi ? h : l;
        }
        size_t idx = blk_idx(row, u);
        *(uint4*)((hi ? Yh : Yl) + idx) = *(uint4*)out;
    }
}

constexpr int NBIG = BATCH * DIM;
constexpr int NW   = DIM * DIM;
constexpr int U_BIG = NBIG / 8;
constexpr int U_W   = NW / 8;
__global__ void split_all_kernel(const float* __restrict__ gI, const float* __restrict__ gT,
                                 const float* __restrict__ Wi, const float* __restrict__ Wt) {
    int gidx = blockIdx.x * blockDim.x + threadIdx.x;
    const float* src; __nv_bfloat16 *H, *L; int unit;
    if (gidx < U_BIG)                { src = gI; H = g_gIr_h; L = g_gIr_l; unit = gidx; }
    else if (gidx < 2 * U_BIG)       { src = gT; H = g_gTr_h; L = g_gTr_l; unit = gidx - U_BIG; }
    else if (gidx < 2 * U_BIG + U_W) { src = Wi; H = g_Wi_h;  L = g_Wi_l;  unit = gidx - 2 * U_BIG; }
    else                             { src = Wt; H = g_Wt_h;  L = g_Wt_l;  unit = gidx - 2 * U_BIG - U_W; }
    int row = unit >> 6, u = unit & 63;
    const float4* s4 = (const float4*)(src + (size_t)row * DIM + u * 8);
    float4 a = s4[0], b = s4[1];
    float vals[8] = {a.x, a.y, a.z, a.w, b.x, b.y, b.z, b.w};
    __nv_bfloat16 h[8], l[8];
#pragma unroll
    for (int e = 0; e < 8; e++) split_bf16(vals[e], h[e], l[e]);
    size_t idx = blk_idx(row, u);
    *(uint4*)(H + idx) = *(uint4*)h;
    *(uint4*)(L + idx) = *(uint4*)l;
}

// ---------------- value-only merge network helpers ----------------
__device__ __forceinline__ void cev(float* d, int i, int j) {
    float hi = fmaxf(d[i], d[j]);
    float lo = fminf(d[i], d[j]);
    d[i] = hi; d[j] = lo;
}
__device__ __forceinline__ void vresort8(float* d) {
    cev(d, 0, 4); cev(d, 1, 5); cev(d, 2, 6); cev(d, 3, 7);
    cev(d, 0, 2); cev(d, 1, 3); cev(d, 4, 6); cev(d, 5, 7);
    cev(d, 0, 1); cev(d, 2, 3); cev(d, 4, 5); cev(d, 6, 7);
}
__device__ __forceinline__ void vmerge8(float* d, int off) {
    float pd[K8];
#pragma unroll
    for (int i = 0; i < K8; i++) pd[i] = __shfl_xor_sync(0xffffffffu, d[i], off);
#pragma unroll
    for (int i = 0; i < K8; i++) d[i] = fmaxf(d[i], pd[K8 - 1 - i]);
    vresort8(d);
}

// ---------------- row top-8 + softmax (R15 proven) ----------------
__global__ void row_topk_kernel(const float* __restrict__ S) {
    __shared__ float swv[8 * K8];
    __shared__ float s_v8;
    __shared__ float cv[64];
    __shared__ int   ci[64];
    __shared__ int   s_cnt;
    const int row = blockIdx.x, tid = threadIdx.x;
    const int wid = tid >> 5, lane = tid & 31;
    const float4* Sr4 = (const float4*)(S + (size_t)row * BATCH);

    if (tid == 0) s_cnt = 0;

    float4 v[8];
#pragma unroll
    for (int it = 0; it < 8; it++) v[it] = Sr4[it * 256 + tid];

    float tv[K8];
#pragma unroll
    for (int t = 0; t < K8; t++) tv[t] = -1e30f;

#pragma unroll
    for (int it = 0; it < 8; it++) {
        float m4 = fmaxf(fmaxf(v[it].x, v[it].y), fmaxf(v[it].z, v[it].w));
        if (m4 > tv[0]) {
            float vals[4] = {v[it].x, v[it].y, v[it].z, v[it].w};
#pragma unroll
            for (int e = 0; e < 4; e++) {
                float x = vals[e];
                if (x > tv[0]) {
                    tv[0] = x;
#pragma unroll
                    for (int q = 0; q < K8 - 1; q++) {
                        float lo = fminf(tv[q], tv[q + 1]);
                        float hi = fmaxf(tv[q], tv[q + 1]);
                        tv[q] = lo; tv[q + 1] = hi;
                    }
                }
            }
        }
    }

    float d[K8];
#pragma unroll
    for (int i = 0; i < K8; i++) d[i] = tv[K8 - 1 - i];
    vmerge8(d, 16); vmerge8(d, 8); vmerge8(d, 4); vmerge8(d, 2); vmerge8(d, 1);

    if (lane == 0) {
#pragma unroll
        for (int i = 0; i < K8; i++) swv[wid * K8 + i] = d[i];
    }
    __syncthreads();

    if (wid == 0) {
        int src = lane & 7;
#pragma unroll
        for (int i = 0; i < K8; i++) d[i] = swv[src * K8 + i];
        vmerge8(d, 4); vmerge8(d, 2); vmerge8(d, 1);
        if (lane == 0) s_v8 = d[K8 - 1];
    }
    __syncthreads();

    const float v8 = s_v8;
#pragma unroll
    for (int it = 0; it < 8; it++) {
        float m4 = fmaxf(fmaxf(v[it].x, v[it].y), fmaxf(v[it].z, v[it].w));
        if (m4 >= v8) {
            float vals[4] = {v[it].x, v[it].y, v[it].z, v[it].w};
            int base = (it * 256 + tid) * 4;
#pragma unroll
            for (int e = 0; e < 4; e++) {
                if (vals[e] >= v8) {
                    int p = atomicAdd(&s_cnt, 1);
                    if (p < 64) { cv[p] = vals[e]; ci[p] = base + e; }
                }
            }
        }
    }
    __syncthreads();

    if (tid == 0) {
        int n = s_cnt < 64 ? s_cnt : 64;
        float outv[K8]; int outi[K8];
#pragma unroll
        for (int sel = 0; sel < K8; sel++) {
            float m = -1e30f; int mi = 0x7fffffff; int mk = 0;
            for (int k = 0; k < n; k++) {
                float x = cv[k];
                if (x > m || (x == m && ci[k] < mi)) { m = x; mi = ci[k]; mk = k; }
            }
            outv[sel] = m; outi[sel] = mi;
            cv[mk] = -1e30f;
        }
        float w[K8]; float s = 0.0f;
#pragma unroll
        for (int j = 0; j < K8; j++) { w[j] = expf(outv[j] - outv[0]); s += w[j]; }
        float inv = 1.0f / s;
#pragma unroll
        for (int j = 0; j < K8; j++) {
            g_rowW[row * K8 + j] = w[j] * inv;
            g_rowI[row * K8 + j] = outi[j];
        }
    }
}

// ---------------- column top-8: 8x batched loads ----------------
__global__ void col_topk_part(const float* __restrict__ S) {
    const int c  = blockIdx.x * blockDim.x + threadIdx.x;
    const int ch = blockIdx.y;
    const int rows = BATCH / NCH;
    const int r0 = ch * rows;

    float tv[K8]; int ti[K8];
#pragma unroll
    for (int t = 0; t < K8; t++) { tv[t] = -1e30f; ti[t] = 0; }

    const float* p = S + (size_t)r0 * BATCH + c;
    for (int r = 0; r < rows; r += 8) {
        float vals[8];
#pragma unroll
        for (int e = 0; e < 8; e++) vals[e] = p[(size_t)(r + e) * BATCH];
        float m8 = vals[0];
#pragma unroll
        for (int e = 1; e < 8; e++) m8 = fmaxf(m8, vals[e]);
        if (m8 > tv[0]) {
#pragma unroll
            for (int e = 0; e < 8; e++) {
                float v = vals[e];
                if (v > tv[0]) {
                    tv[0] = v; ti[0] = r0 + r + e;
#pragma unroll
                    for (int q = 0; q < K8 - 1; q++) {
                        if (tv[q] > tv[q + 1]) {
                            float a = tv[q]; tv[q] = tv[q + 1]; tv[q + 1] = a;
                            int b = ti[q]; ti[q] = ti[q + 1]; ti[q + 1] = b;
                        }
                    }
                }
            }
        }
    }
    size_t base = ((size_t)ch * BATCH + c) * K8;
#pragma unroll
    for (int t = 0; t < K8; t++) { g_cpV[base + t] = tv[t]; g_cpI[base + t] = ti[t]; }
}

__global__ void col_merge_softmax() {
    const int c = blockIdx.x * blockDim.x + threadIdx.x;
    float tv[K8]; int ti[K8];
#pragma unroll
    for (int t = 0; t < K8; t++) { tv[t] = -1e30f; ti[t] = 0; }

    for (int ch = 0; ch < NCH; ch++) {
        size_t base = ((size_t)ch * BATCH + c) * K8;
#pragma unroll
        for (int t = 0; t < K8; t++) {
            float v = g_cpV[base + t];
            if (v > tv[0]) {
                int vi = g_cpI[base + t];
                tv[0] = v; ti[0] = vi;
#pragma unroll
                for (int q = 0; q < K8 - 1; q++) {
                    if (tv[q] > tv[q + 1]) {
                        float a = tv[q]; tv[q] = tv[q + 1]; tv[q + 1] = a;
                        int b = ti[q]; ti[q] = ti[q + 1]; ti[q + 1] = b;
                    }
                }
            }
        }
    }
    float mx = tv[K8 - 1];
    float w[K8]; float s = 0.0f;
#pragma unroll
    for (int t = 0; t < K8; t++) { w[t] = expf(tv[t] - mx); s += w[t]; }
    float inv = 1.0f / s;
#pragma unroll
    for (int t = 0; t < K8; t++) {
        g_colW[c * K8 + t] = w[t] * inv;
        g_colI[c * K8 + t] = ti[t];
    }
}

// ---------------- sparse message + residual + LayerNorm ----------------
__global__ void msg_ln_kernel(const float* __restrict__ X, const float* __restrict__ P,
                              const float* __restrict__ W, const int* __restrict__ IDX,
                              const float* __restrict__ gamma, const float* __restrict__ beta,
                              float* __restrict__ out) {
    __shared__ float sbuf[256];
    __shared__ float sw[K8];
    __shared__ int   sidx[K8];
    const int row = blockIdx.x, tid = threadIdx.x;
    if (tid < K8) { sw[tid] = W[row * K8 + tid]; sidx[tid] = IDX[row * K8 + tid]; }
    __syncthreads();

    float m0 = 0.0f, m1 = 0.0f;
#pragma unroll
    for (int j = 0; j < K8; j++) {
        const float* pr = P + (size_t)sidx[j] * DIM;
        float w = sw[j];
        m0 = fmaf(w, pr[tid], m0);
        m1 = fmaf(w, pr[tid + 256], m1);
    }
    float x0 = X[(size_t)row * DIM + tid]       + ALPHA * m0;
    float x1 = X[(size_t)row * DIM + tid + 256] + ALPHA * m1;

    sbuf[tid] = x0 + x1;
    __syncthreads();
    for (int s = 128; s > 0; s >>= 1) { if (tid < s) sbuf[tid] += sbuf[tid + s]; __syncthreads(); }
    float mu = sbuf[0] * (1.0f / DIM);
    __syncthreads();

    float d0 = x0 - mu, d1 = x1 - mu;
    sbuf[tid] = d0 * d0 + d1 * d1;
    __syncthreads();
    for (int s = 128; s > 0; s >>= 1) { if (tid < s) sbuf[tid] += sbuf[tid + s]; __syncthreads(); }
    float var = sbuf[0] * (1.0f / DIM);
    float rstd = rsqrtf(var + LN_EPS);

    out[(size_t)row * DIM + tid]       = d0 * rstd * gamma[tid]       + beta[tid];
    out[(size_t)row * DIM + tid + 256] = d1 * rstd * gamma[tid + 256] + beta[tid + 256];
}

// ---------------- launch: fully serial; col_topk_part 4th for ncu ----------------
extern "C" void kernel_launch(void* const* d_in, const int* in_sizes, int n_in,
                              void* d_out, int out_size) {
    const float* gI      = (const float*)d_in[0];
    const float* gT      = (const float*)d_in[1];
    const float* Wi      = (const float*)d_in[2];
    const float* Wt      = (const float*)d_in[3];
    const float* gamma_i = (const float*)d_in[4];
    const float* beta_i  = (const float*)d_in[5];
    const float* gamma_t = (const float*)d_in[6];
    const float* beta_t  = (const float*)d_in[7];

    float* out = (float*)d_out;
    float* gI2 = out;
    float* gT2 = out + (size_t)BATCH * DIM;
    float* S   = out + 2 * (size_t)BATCH * DIM;

    cudaFuncSetAttribute(gemm_mma, cudaFuncAttributeMaxDynamicSharedMemorySize, SMEM_DYN);

    void *p_gi_h, *p_gi_l, *p_gt_h, *p_gt_l;
    void *p_gIr_h, *p_gIr_l, *p_gTr_h, *p_gTr_l;
    void *p_Wi_h, *p_Wi_l, *p_Wt_h, *p_Wt_l;
    void *p_PT, *p_PI, *p_rowW, *p_rowI, *p_colW, *p_colI;
    cudaGetSymbolAddress(&p_gi_h, g_gi_h);   cudaGetSymbolAddress(&p_gi_l, g_gi_l);
    cudaGetSymbolAddress(&p_gt_h, g_gt_h);   cudaGetSymbolAddress(&p_gt_l, g_gt_l);
    cudaGetSymbolAddress(&p_gIr_h, g_gIr_h); cudaGetSymbolAddress(&p_gIr_l, g_gIr_l);
    cudaGetSymbolAddress(&p_gTr_h, g_gTr_h); cudaGetSymbolAddress(&p_gTr_l, g_gTr_l);
    cudaGetSymbolAddress(&p_Wi_h, g_Wi_h);   cudaGetSymbolAddress(&p_Wi_l, g_Wi_l);
    cudaGetSymbolAddress(&p_Wt_h, g_Wt_h);   cudaGetSymbolAddress(&p_Wt_l, g_Wt_l);
    cudaGetSymbolAddress(&p_PT, g_PT);       cudaGetSymbolAddress(&p_PI, g_PI);
    cudaGetSymbolAddress(&p_rowW, g_rowW);   cudaGetSymbolAddress(&p_rowI, g_rowI);
    cudaGetSymbolAddress(&p_colW, g_colW);   cudaGetSymbolAddress(&p_colI, g_colI);

    // (1)(2) normalize + split for S
    rownorm_split_kernel<<<BATCH, 256>>>(gI, (__nv_bfloat16*)p_gi_h, (__nv_bfloat16*)p_gi_l);
    rownorm_split_kernel<<<BATCH, 256>>>(gT, (__nv_bfloat16*)p_gt_h, (__nv_bfloat16*)p_gt_l);

    // (3) S = (gi @ gt^T) / tau
    gemm_mma<<<dim3(BATCH / BN, BATCH / BM), 256, SMEM_DYN>>>(
        (const __nv_bfloat16*)p_gi_h, (const __nv_bfloat16*)p_gi_l,
        (const __nv_bfloat16*)p_gt_h, (const __nv_bfloat16*)p_gt_l,
        S, BATCH, INV_TAU);

    // (4) column top-8 partials   <-- 4th launch: profiled by ncu
    col_topk_part<<<dim3(BATCH / 256, NCH), 256>>>(S);
    col_merge_softmax<<<BATCH / 256, 256>>>();

    // (6) row top-8 softmax
    row_topk_kernel<<<BATCH, 256>>>(S);

    // (7) fused split of gI, gT, Wi, Wt
    constexpr int NTOT = 2 * U_BIG + 2 * U_W;
    split_all_kernel<<<NTOT / 256, 256>>>(gI, gT, Wi, Wt);

    // (8)(9) projections
    gemm_mma<<<dim3(DIM / BN, BATCH / BM), 256, SMEM_DYN>>>(
        (const __nv_bfloat16*)p_gTr_h, (const __nv_bfloat16*)p_gTr_l,
        (const __nv_bfloat16*)p_Wt_h,  (const __nv_bfloat16*)p_Wt_l,
        (float*)p_PT, DIM, 1.0f);
    gemm_mma<<<dim3(DIM / BN, BATCH / BM), 256, SMEM_DYN>>>(
        (const __nv_bfloat16*)p_gIr_h, (const __nv_bfloat16*)p_gIr_l,
        (const __nv_bfloat16*)p_Wi_h,  (const __nv_bfloat16*)p_Wi_l,
        (float*)p_PI, DIM, 1.0f);

    // (10)(11) messages + residual + LayerNorm
    msg_ln_kernel<<<BATCH, 256>>>(gI, (const float*)p_PT, (const float*)p_rowW,
                                  (const int*)p_rowI, gamma_i, beta_i, gI2);
    msg_ln_kernel<<<BATCH, 256>>>(gT, (const float*)p_PI, (const float*)p_colW,
                                  (const int*)p_colI, gamma_t, beta_t, gT2);
}